// round 3
// baseline (speedup 1.0000x reference)
#include <cuda_runtime.h>
#include <cuda_bf16.h>
#include <math.h>

// Problem constants
#define BB 64
#define NN 307
#define TT 64
#define FF 3
#define HH 64
#define ROWS (NN * BB)          // 19648 rows of (N,B,H)-laid-out state
#define COLS (BB * HH)          // 4096

// Persistent scratch (allocation-free rule: __device__ globals)
__device__ float g_z[ROWS * HH];
__device__ float g_b1[ROWS * HH];
__device__ float g_b2[ROWS * HH];

__device__ __forceinline__ float warp_sum(float v) {
#pragma unroll
    for (int o = 16; o > 0; o >>= 1) v += __shfl_xor_sync(0xffffffffu, v, o);
    return v;
}

// ---------------------------------------------------------------------------
// GEMM: Out[307 x 4096] = A[307 x 307] @ In[307 x 4096]   (fp32, tiled)
// ---------------------------------------------------------------------------
__global__ void __launch_bounds__(256) gemmA_kernel(const float* __restrict__ A,
                                                    const float* __restrict__ In,
                                                    float* __restrict__ Out) {
    __shared__ float As[16][64];
    __shared__ float Bs[16][64];
    const int tid = threadIdx.x;
    const int tx = tid & 15, ty = tid >> 4;
    const int row0 = blockIdx.y * 64;
    const int col0 = blockIdx.x * 64;

    float acc[4][4];
#pragma unroll
    for (int i = 0; i < 4; i++)
#pragma unroll
        for (int j = 0; j < 4; j++) acc[i][j] = 0.f;

    const int am = tid >> 2;            // 0..63 (m within tile)
    const int ak = (tid & 3) * 4;       // 0,4,8,12
    const int bk = tid >> 4;            // 0..15
    const int bn = (tid & 15) * 4;      // 0..60

    for (int k0 = 0; k0 < NN; k0 += 16) {
        const int gr = row0 + am;
#pragma unroll
        for (int i = 0; i < 4; i++) {
            const int k = k0 + ak + i;
            As[ak + i][am] = (gr < NN && k < NN) ? A[gr * NN + k] : 0.f;
        }
        const int gk = k0 + bk;
        float4 v = make_float4(0.f, 0.f, 0.f, 0.f);
        if (gk < NN) v = *reinterpret_cast<const float4*>(In + (size_t)gk * COLS + col0 + bn);
        *reinterpret_cast<float4*>(&Bs[bk][bn]) = v;
        __syncthreads();
#pragma unroll
        for (int k = 0; k < 16; k++) {
            const float4 ra = *reinterpret_cast<const float4*>(&As[k][ty * 4]);
            const float4 rb = *reinterpret_cast<const float4*>(&Bs[k][tx * 4]);
            const float a4[4] = {ra.x, ra.y, ra.z, ra.w};
            const float b4[4] = {rb.x, rb.y, rb.z, rb.w};
#pragma unroll
            for (int i = 0; i < 4; i++)
#pragma unroll
                for (int j = 0; j < 4; j++) acc[i][j] += a4[i] * b4[j];
        }
        __syncthreads();
    }
#pragma unroll
    for (int i = 0; i < 4; i++) {
        const int r = row0 + ty * 4 + i;
        if (r < NN) {
            float4 o = make_float4(acc[i][0], acc[i][1], acc[i][2], acc[i][3]);
            *reinterpret_cast<float4*>(Out + (size_t)r * COLS + col0 + tx * 4) = o;
        }
    }
}

// ---------------------------------------------------------------------------
// out[r,h] = tanh( in[r,:] @ W[64x64] )   ; 32 threads per row, 2 h per thread
// grid 614 blocks * 32 rows
// ---------------------------------------------------------------------------
__global__ void __launch_bounds__(256) gc_kernel(const float* __restrict__ in,
                                                 const float* __restrict__ W,
                                                 float* __restrict__ out) {
    __shared__ float Ws[4096];
    __shared__ float rows[8][64];
    const int tid = threadIdx.x;
    for (int i = tid; i < 4096; i += 256) Ws[i] = W[i];
    __syncthreads();
    const int lane = tid & 31, rl = tid >> 5;
    const int h0 = 2 * lane, h1 = h0 + 1;
    for (int it = 0; it < 4; it++) {
        const int r = blockIdx.x * 32 + it * 8 + rl;
        __syncwarp();
        const float2 rv = *reinterpret_cast<const float2*>(in + (size_t)r * HH + h0);
        rows[rl][h0] = rv.x; rows[rl][h1] = rv.y;
        __syncwarp();
        float a0 = 0.f, a1 = 0.f;
#pragma unroll
        for (int k = 0; k < 64; k++) {
            const float c = rows[rl][k];
            const float2 w = *reinterpret_cast<const float2*>(&Ws[k * 64 + h0]);
            a0 += c * w.x; a1 += c * w.y;
        }
        *reinterpret_cast<float2*>(out + (size_t)r * HH + h0) =
            make_float2(tanhf(a0), tanhf(a1));
    }
}

// ---------------------------------------------------------------------------
// z[r,:] = 2*z[r,:] + LayerNorm( tanh( AH[r,:] @ W2 ) ) * g + b
// ---------------------------------------------------------------------------
__global__ void __launch_bounds__(256) c1_kernel(const float* __restrict__ AH,
                                                 const float* __restrict__ W2,
                                                 const float* __restrict__ ln_g,
                                                 const float* __restrict__ ln_b,
                                                 float* __restrict__ z) {
    __shared__ float Ws[4096];
    __shared__ float rows[8][64];
    __shared__ float gs[64], bs[64];
    const int tid = threadIdx.x;
    for (int i = tid; i < 4096; i += 256) Ws[i] = W2[i];
    if (tid < 64) { gs[tid] = ln_g[tid]; bs[tid] = ln_b[tid]; }
    __syncthreads();
    const int lane = tid & 31, rl = tid >> 5;
    const int h0 = 2 * lane, h1 = h0 + 1;
    for (int it = 0; it < 4; it++) {
        const int r = blockIdx.x * 32 + it * 8 + rl;
        __syncwarp();
        const float2 rv = *reinterpret_cast<const float2*>(AH + (size_t)r * HH + h0);
        rows[rl][h0] = rv.x; rows[rl][h1] = rv.y;
        __syncwarp();
        float a0 = 0.f, a1 = 0.f;
#pragma unroll
        for (int k = 0; k < 64; k++) {
            const float c = rows[rl][k];
            const float2 w = *reinterpret_cast<const float2*>(&Ws[k * 64 + h0]);
            a0 += c * w.x; a1 += c * w.y;
        }
        const float ha = tanhf(a0), hb = tanhf(a1);
        const float mu = warp_sum(ha + hb) * (1.f / 64.f);
        const float da = ha - mu, db = hb - mu;
        const float var = warp_sum(da * da + db * db) * (1.f / 64.f);
        const float rstd = rsqrtf(var + 1e-5f);
        const float d0 = da * rstd * gs[h0] + bs[h0];
        const float d1 = db * rstd * gs[h1] + bs[h1];
        float2* zp = reinterpret_cast<float2*>(z + (size_t)r * HH + h0);
        const float2 zv = *zp;
        *zp = make_float2(2.f * zv.x + d0, 2.f * zv.y + d1);
    }
}

// ---------------------------------------------------------------------------
// z_obs / gate / masked update / pred write (timestep t1 = t+1)
// ---------------------------------------------------------------------------
__global__ void __launch_bounds__(256) c2_kernel(const float* __restrict__ x_seq,
                                                 const float* __restrict__ obs_mask,
                                                 const float* __restrict__ W_obs,
                                                 const float* __restrict__ b_obs,
                                                 const float* __restrict__ W_gate,
                                                 const float* __restrict__ b_gate,
                                                 const float* __restrict__ W_dec,
                                                 const float* __restrict__ b_dec,
                                                 float* __restrict__ z,
                                                 float* __restrict__ preds,
                                                 int t1) {
    __shared__ float Wg[128 * 64];
    __shared__ float cat[8][128];
    __shared__ float Wo[192], bo[64], bg[64], wd[64];
    const int tid = threadIdx.x;
    for (int i = tid; i < 8192; i += 256) Wg[i] = W_gate[i];
    if (tid < 192) Wo[tid] = W_obs[tid];
    if (tid < 64) { bo[tid] = b_obs[tid]; bg[tid] = b_gate[tid]; wd[tid] = W_dec[tid]; }
    __syncthreads();
    const int lane = tid & 31, rl = tid >> 5;
    const int h0 = 2 * lane, h1 = h0 + 1;
    const float bdec = b_dec[0];
    for (int it = 0; it < 4; it++) {
        const int r = blockIdx.x * 32 + it * 8 + rl;
        const int n = r >> 6, b = r & 63;
        const float2 zv = *reinterpret_cast<const float2*>(z + (size_t)r * HH + h0);
        const float* x = x_seq + ((size_t)(b * NN + n) * TT + t1) * FF;
        const float x0 = x[0], x1 = x[1], x2 = x[2];
        const float zo0 = bo[h0] + x0 * Wo[h0] + x1 * Wo[64 + h0] + x2 * Wo[128 + h0];
        const float zo1 = bo[h1] + x0 * Wo[h1] + x1 * Wo[64 + h1] + x2 * Wo[128 + h1];
        __syncwarp();
        cat[rl][h0] = zv.x; cat[rl][h1] = zv.y;
        cat[rl][64 + h0] = zo0; cat[rl][64 + h1] = zo1;
        __syncwarp();
        float a0 = bg[h0], a1 = bg[h1];
#pragma unroll
        for (int k = 0; k < 128; k++) {
            const float c = cat[rl][k];
            const float2 w = *reinterpret_cast<const float2*>(&Wg[k * 64 + h0]);
            a0 += c * w.x; a1 += c * w.y;
        }
        const float g0 = 1.f / (1.f + __expf(-a0));
        const float g1 = 1.f / (1.f + __expf(-a1));
        const float m = obs_mask[b * NN + n];
        const float zf0 = zv.x + g0 * (zo0 - zv.x) * m;
        const float zf1 = zv.y + g1 * (zo1 - zv.y) * m;
        *reinterpret_cast<float2*>(z + (size_t)r * HH + h0) = make_float2(zf0, zf1);
        const float p = warp_sum(zf0 * wd[h0] + zf1 * wd[h1]);
        if (lane == 0) preds[(size_t)(b * NN + n) * TT + t1] = p + bdec;
    }
}

// ---------------------------------------------------------------------------
// Encoder: z0 = x[:,:,0,:] @ W_enc + b_enc ; preds[...,0] = dec(z0)
// ---------------------------------------------------------------------------
__global__ void __launch_bounds__(256) enc_kernel(const float* __restrict__ x_seq,
                                                  const float* __restrict__ W_enc,
                                                  const float* __restrict__ b_enc,
                                                  const float* __restrict__ W_dec,
                                                  const float* __restrict__ b_dec,
                                                  float* __restrict__ z,
                                                  float* __restrict__ preds) {
    const int tid = threadIdx.x;
    const int lane = tid & 31;
    const int r = blockIdx.x * 8 + (tid >> 5);
    const int n = r >> 6, b = r & 63;
    const float* x = x_seq + (size_t)(b * NN + n) * TT * FF;  // t = 0
    const float x0 = x[0], x1 = x[1], x2 = x[2];
    const int h0 = 2 * lane, h1 = h0 + 1;
    const float za = b_enc[h0] + x0 * W_enc[h0] + x1 * W_enc[64 + h0] + x2 * W_enc[128 + h0];
    const float zb = b_enc[h1] + x0 * W_enc[h1] + x1 * W_enc[64 + h1] + x2 * W_enc[128 + h1];
    *reinterpret_cast<float2*>(z + (size_t)r * HH + h0) = make_float2(za, zb);
    const float p = warp_sum(za * W_dec[h0] + zb * W_dec[h1]);
    if (lane == 0) preds[(size_t)(b * NN + n) * TT + 0] = p + b_dec[0];
}

// ---------------------------------------------------------------------------
extern "C" void kernel_launch(void* const* d_in, const int* in_sizes, int n_in,
                              void* d_out, int out_size) {
    const float* x_seq   = (const float*)d_in[0];
    const float* obs_mask= (const float*)d_in[1];
    const float* A       = (const float*)d_in[2];
    const float* W_enc   = (const float*)d_in[3];
    const float* b_enc   = (const float*)d_in[4];
    const float* W_gc1   = (const float*)d_in[5];
    const float* W_gc2   = (const float*)d_in[6];
    const float* ln_g    = (const float*)d_in[7];
    const float* ln_b    = (const float*)d_in[8];
    const float* W_obs   = (const float*)d_in[9];
    const float* b_obs   = (const float*)d_in[10];
    const float* W_gate  = (const float*)d_in[11];
    const float* b_gate  = (const float*)d_in[12];
    const float* W_dec   = (const float*)d_in[13];
    const float* b_dec   = (const float*)d_in[14];
    float* preds = (float*)d_out;

    float *z, *b1, *b2;
    cudaGetSymbolAddress((void**)&z,  g_z);
    cudaGetSymbolAddress((void**)&b1, g_b1);
    cudaGetSymbolAddress((void**)&b2, g_b2);

    enc_kernel<<<ROWS / 8, 256>>>(x_seq, W_enc, b_enc, W_dec, b_dec, z, preds);

    const dim3 ggrid(COLS / 64, (NN + 63) / 64);   // 64 x 5
    for (int t = 0; t < TT - 1; t++) {
        gemmA_kernel<<<ggrid, 256>>>(A, z, b1);
        gc_kernel<<<ROWS / 32, 256>>>(b1, W_gc1, b2);
        gemmA_kernel<<<ggrid, 256>>>(A, b2, b1);
        c1_kernel<<<ROWS / 32, 256>>>(b1, W_gc2, ln_g, ln_b, z);
        c2_kernel<<<ROWS / 32, 256>>>(x_seq, obs_mask, W_obs, b_obs,
                                      W_gate, b_gate, W_dec, b_dec,
                                      z, preds, t + 1);
    }
}

// round 4
// speedup vs baseline: 1.0024x; 1.0024x over previous
#include <cuda_runtime.h>
#include <cuda_bf16.h>
#include <math.h>

// Problem constants
#define BB 64
#define NN 307
#define TT 64
#define FF 3
#define HH 64
#define ROWS (NN * BB)          // 19648 rows of (N,B,H)-laid-out state
#define COLS (BB * HH)          // 4096

// Persistent scratch (allocation-free rule: __device__ globals)
__device__ float g_z[ROWS * HH];
__device__ float g_b1[ROWS * HH];
__device__ float g_b2[ROWS * HH];

__device__ __forceinline__ float warp_sum(float v) {
#pragma unroll
    for (int o = 16; o > 0; o >>= 1) v += __shfl_xor_sync(0xffffffffu, v, o);
    return v;
}

// ---------------------------------------------------------------------------
// GEMM: Out[307 x 4096] = A[307 x 307] @ In[307 x 4096]   (fp32, tiled)
// ---------------------------------------------------------------------------
__global__ void __launch_bounds__(256) gemmA_kernel(const float* __restrict__ A,
                                                    const float* __restrict__ In,
                                                    float* __restrict__ Out) {
    __shared__ float As[16][64];
    __shared__ float Bs[16][64];
    const int tid = threadIdx.x;
    const int tx = tid & 15, ty = tid >> 4;
    const int row0 = blockIdx.y * 64;
    const int col0 = blockIdx.x * 64;

    float acc[4][4];
#pragma unroll
    for (int i = 0; i < 4; i++)
#pragma unroll
        for (int j = 0; j < 4; j++) acc[i][j] = 0.f;

    const int am = tid >> 2;            // 0..63 (m within tile)
    const int ak = (tid & 3) * 4;       // 0,4,8,12
    const int bk = tid >> 4;            // 0..15
    const int bn = (tid & 15) * 4;      // 0..60

    for (int k0 = 0; k0 < NN; k0 += 16) {
        const int gr = row0 + am;
#pragma unroll
        for (int i = 0; i < 4; i++) {
            const int k = k0 + ak + i;
            As[ak + i][am] = (gr < NN && k < NN) ? A[gr * NN + k] : 0.f;
        }
        const int gk = k0 + bk;
        float4 v = make_float4(0.f, 0.f, 0.f, 0.f);
        if (gk < NN) v = *reinterpret_cast<const float4*>(In + (size_t)gk * COLS + col0 + bn);
        *reinterpret_cast<float4*>(&Bs[bk][bn]) = v;
        __syncthreads();
#pragma unroll
        for (int k = 0; k < 16; k++) {
            const float4 ra = *reinterpret_cast<const float4*>(&As[k][ty * 4]);
            const float4 rb = *reinterpret_cast<const float4*>(&Bs[k][tx * 4]);
            const float a4[4] = {ra.x, ra.y, ra.z, ra.w};
            const float b4[4] = {rb.x, rb.y, rb.z, rb.w};
#pragma unroll
            for (int i = 0; i < 4; i++)
#pragma unroll
                for (int j = 0; j < 4; j++) acc[i][j] += a4[i] * b4[j];
        }
        __syncthreads();
    }
#pragma unroll
    for (int i = 0; i < 4; i++) {
        const int r = row0 + ty * 4 + i;
        if (r < NN) {
            float4 o = make_float4(acc[i][0], acc[i][1], acc[i][2], acc[i][3]);
            *reinterpret_cast<float4*>(Out + (size_t)r * COLS + col0 + tx * 4) = o;
        }
    }
}

// ---------------------------------------------------------------------------
// out[r,h] = tanh( in[r,:] @ W[64x64] )   ; 32 threads per row, 2 h per thread
// grid 614 blocks * 32 rows
// ---------------------------------------------------------------------------
__global__ void __launch_bounds__(256) gc_kernel(const float* __restrict__ in,
                                                 const float* __restrict__ W,
                                                 float* __restrict__ out) {
    __shared__ float Ws[4096];
    __shared__ float rows[8][64];
    const int tid = threadIdx.x;
    for (int i = tid; i < 4096; i += 256) Ws[i] = W[i];
    __syncthreads();
    const int lane = tid & 31, rl = tid >> 5;
    const int h0 = 2 * lane, h1 = h0 + 1;
    for (int it = 0; it < 4; it++) {
        const int r = blockIdx.x * 32 + it * 8 + rl;
        __syncwarp();
        const float2 rv = *reinterpret_cast<const float2*>(in + (size_t)r * HH + h0);
        rows[rl][h0] = rv.x; rows[rl][h1] = rv.y;
        __syncwarp();
        float a0 = 0.f, a1 = 0.f;
#pragma unroll
        for (int k = 0; k < 64; k++) {
            const float c = rows[rl][k];
            const float2 w = *reinterpret_cast<const float2*>(&Ws[k * 64 + h0]);
            a0 += c * w.x; a1 += c * w.y;
        }
        *reinterpret_cast<float2*>(out + (size_t)r * HH + h0) =
            make_float2(tanhf(a0), tanhf(a1));
    }
}

// ---------------------------------------------------------------------------
// z[r,:] = 2*z[r,:] + LayerNorm( tanh( AH[r,:] @ W2 ) ) * g + b
// ---------------------------------------------------------------------------
__global__ void __launch_bounds__(256) c1_kernel(const float* __restrict__ AH,
                                                 const float* __restrict__ W2,
                                                 const float* __restrict__ ln_g,
                                                 const float* __restrict__ ln_b,
                                                 float* __restrict__ z) {
    __shared__ float Ws[4096];
    __shared__ float rows[8][64];
    __shared__ float gs[64], bs[64];
    const int tid = threadIdx.x;
    for (int i = tid; i < 4096; i += 256) Ws[i] = W2[i];
    if (tid < 64) { gs[tid] = ln_g[tid]; bs[tid] = ln_b[tid]; }
    __syncthreads();
    const int lane = tid & 31, rl = tid >> 5;
    const int h0 = 2 * lane, h1 = h0 + 1;
    for (int it = 0; it < 4; it++) {
        const int r = blockIdx.x * 32 + it * 8 + rl;
        __syncwarp();
        const float2 rv = *reinterpret_cast<const float2*>(AH + (size_t)r * HH + h0);
        rows[rl][h0] = rv.x; rows[rl][h1] = rv.y;
        __syncwarp();
        float a0 = 0.f, a1 = 0.f;
#pragma unroll
        for (int k = 0; k < 64; k++) {
            const float c = rows[rl][k];
            const float2 w = *reinterpret_cast<const float2*>(&Ws[k * 64 + h0]);
            a0 += c * w.x; a1 += c * w.y;
        }
        const float ha = tanhf(a0), hb = tanhf(a1);
        const float mu = warp_sum(ha + hb) * (1.f / 64.f);
        const float da = ha - mu, db = hb - mu;
        const float var = warp_sum(da * da + db * db) * (1.f / 64.f);
        const float rstd = rsqrtf(var + 1e-5f);
        const float d0 = da * rstd * gs[h0] + bs[h0];
        const float d1 = db * rstd * gs[h1] + bs[h1];
        float2* zp = reinterpret_cast<float2*>(z + (size_t)r * HH + h0);
        const float2 zv = *zp;
        *zp = make_float2(2.f * zv.x + d0, 2.f * zv.y + d1);
    }
}

// ---------------------------------------------------------------------------
// z_obs / gate / masked update / pred write (timestep t1 = t+1)
// ---------------------------------------------------------------------------
__global__ void __launch_bounds__(256) c2_kernel(const float* __restrict__ x_seq,
                                                 const float* __restrict__ obs_mask,
                                                 const float* __restrict__ W_obs,
                                                 const float* __restrict__ b_obs,
                                                 const float* __restrict__ W_gate,
                                                 const float* __restrict__ b_gate,
                                                 const float* __restrict__ W_dec,
                                                 const float* __restrict__ b_dec,
                                                 float* __restrict__ z,
                                                 float* __restrict__ preds,
                                                 int t1) {
    __shared__ float Wg[128 * 64];
    __shared__ float cat[8][128];
    __shared__ float Wo[192], bo[64], bg[64], wd[64];
    const int tid = threadIdx.x;
    for (int i = tid; i < 8192; i += 256) Wg[i] = W_gate[i];
    if (tid < 192) Wo[tid] = W_obs[tid];
    if (tid < 64) { bo[tid] = b_obs[tid]; bg[tid] = b_gate[tid]; wd[tid] = W_dec[tid]; }
    __syncthreads();
    const int lane = tid & 31, rl = tid >> 5;
    const int h0 = 2 * lane, h1 = h0 + 1;
    const float bdec = b_dec[0];
    for (int it = 0; it < 4; it++) {
        const int r = blockIdx.x * 32 + it * 8 + rl;
        const int n = r >> 6, b = r & 63;
        const float2 zv = *reinterpret_cast<const float2*>(z + (size_t)r * HH + h0);
        const float* x = x_seq + ((size_t)(b * NN + n) * TT + t1) * FF;
        const float x0 = x[0], x1 = x[1], x2 = x[2];
        const float zo0 = bo[h0] + x0 * Wo[h0] + x1 * Wo[64 + h0] + x2 * Wo[128 + h0];
        const float zo1 = bo[h1] + x0 * Wo[h1] + x1 * Wo[64 + h1] + x2 * Wo[128 + h1];
        __syncwarp();
        cat[rl][h0] = zv.x; cat[rl][h1] = zv.y;
        cat[rl][64 + h0] = zo0; cat[rl][64 + h1] = zo1;
        __syncwarp();
        float a0 = bg[h0], a1 = bg[h1];
#pragma unroll
        for (int k = 0; k < 128; k++) {
            const float c = cat[rl][k];
            const float2 w = *reinterpret_cast<const float2*>(&Wg[k * 64 + h0]);
            a0 += c * w.x; a1 += c * w.y;
        }
        const float g0 = 1.f / (1.f + __expf(-a0));
        const float g1 = 1.f / (1.f + __expf(-a1));
        const float m = obs_mask[b * NN + n];
        const float zf0 = zv.x + g0 * (zo0 - zv.x) * m;
        const float zf1 = zv.y + g1 * (zo1 - zv.y) * m;
        *reinterpret_cast<float2*>(z + (size_t)r * HH + h0) = make_float2(zf0, zf1);
        const float p = warp_sum(zf0 * wd[h0] + zf1 * wd[h1]);
        if (lane == 0) preds[(size_t)(b * NN + n) * TT + t1] = p + bdec;
    }
}

// ---------------------------------------------------------------------------
// Encoder: z0 = x[:,:,0,:] @ W_enc + b_enc ; preds[...,0] = dec(z0)
// ---------------------------------------------------------------------------
__global__ void __launch_bounds__(256) enc_kernel(const float* __restrict__ x_seq,
                                                  const float* __restrict__ W_enc,
                                                  const float* __restrict__ b_enc,
                                                  const float* __restrict__ W_dec,
                                                  const float* __restrict__ b_dec,
                                                  float* __restrict__ z,
                                                  float* __restrict__ preds) {
    const int tid = threadIdx.x;
    const int lane = tid & 31;
    const int r = blockIdx.x * 8 + (tid >> 5);
    const int n = r >> 6, b = r & 63;
    const float* x = x_seq + (size_t)(b * NN + n) * TT * FF;  // t = 0
    const float x0 = x[0], x1 = x[1], x2 = x[2];
    const int h0 = 2 * lane, h1 = h0 + 1;
    const float za = b_enc[h0] + x0 * W_enc[h0] + x1 * W_enc[64 + h0] + x2 * W_enc[128 + h0];
    const float zb = b_enc[h1] + x0 * W_enc[h1] + x1 * W_enc[64 + h1] + x2 * W_enc[128 + h1];
    *reinterpret_cast<float2*>(z + (size_t)r * HH + h0) = make_float2(za, zb);
    const float p = warp_sum(za * W_dec[h0] + zb * W_dec[h1]);
    if (lane == 0) preds[(size_t)(b * NN + n) * TT + 0] = p + b_dec[0];
}

// ---------------------------------------------------------------------------
extern "C" void kernel_launch(void* const* d_in, const int* in_sizes, int n_in,
                              void* d_out, int out_size) {
    const float* x_seq   = (const float*)d_in[0];
    const float* obs_mask= (const float*)d_in[1];
    const float* A       = (const float*)d_in[2];
    const float* W_enc   = (const float*)d_in[3];
    const float* b_enc   = (const float*)d_in[4];
    const float* W_gc1   = (const float*)d_in[5];
    const float* W_gc2   = (const float*)d_in[6];
    const float* ln_g    = (const float*)d_in[7];
    const float* ln_b    = (const float*)d_in[8];
    const float* W_obs   = (const float*)d_in[9];
    const float* b_obs   = (const float*)d_in[10];
    const float* W_gate  = (const float*)d_in[11];
    const float* b_gate  = (const float*)d_in[12];
    const float* W_dec   = (const float*)d_in[13];
    const float* b_dec   = (const float*)d_in[14];
    float* preds = (float*)d_out;

    float *z, *b1, *b2;
    cudaGetSymbolAddress((void**)&z,  g_z);
    cudaGetSymbolAddress((void**)&b1, g_b1);
    cudaGetSymbolAddress((void**)&b2, g_b2);

    enc_kernel<<<ROWS / 8, 256>>>(x_seq, W_enc, b_enc, W_dec, b_dec, z, preds);

    const dim3 ggrid(COLS / 64, (NN + 63) / 64);   // 64 x 5
    for (int t = 0; t < TT - 1; t++) {
        gemmA_kernel<<<ggrid, 256>>>(A, z, b1);
        gc_kernel<<<ROWS / 32, 256>>>(b1, W_gc1, b2);
        gemmA_kernel<<<ggrid, 256>>>(A, b2, b1);
        c1_kernel<<<ROWS / 32, 256>>>(b1, W_gc2, ln_g, ln_b, z);
        c2_kernel<<<ROWS / 32, 256>>>(x_seq, obs_mask, W_obs, b_obs,
                                      W_gate, b_gate, W_dec, b_dec,
                                      z, preds, t + 1);
    }
}

// round 12
// speedup vs baseline: 1.1354x; 1.1327x over previous
#include <cuda_runtime.h>
#include <cuda_bf16.h>
#include <stdint.h>
#include <math.h>

// Problem constants
#define BB 64
#define NN 307
#define TT 64
#define FF 3
#define HH 64
#define ROWS (NN * BB)          // 19648
#define COLS (BB * HH)          // 4096

// Split-bf16 GEMM: Out[384 x 4096] = A2[384 x 640] @ Z2[640 x 4096]
// A2 = [A_hi | A_lo], Z2 = [Z_hi ; Z_lo] (k-major).
// chunk ch: seg=ch/5, kk=(ch%5)*64; a_off = kk + (seg==1?320:0); b_off = kk + (seg==2?320:0)
// (drops only the A_lo@Z_lo term, ~2^-18 relative)
#define KSEG 320
#define KA   640
#define MPAD 384
#define KC   64
#define NCH  15
#define MT   128
#define NT   64
#define PA   72     // smA pitch (bf16 units) = 144B -> conflict-free frag loads
#define PB   76     // smB pitch (bf16 units) = 152B

// Persistent scratch (__device__ globals; zero-init -> padding rows/cols stay 0)
__device__ __align__(256) float         g_z [ROWS * HH];
__device__ __align__(256) float         g_b1[ROWS * HH];
__device__ __align__(256) __nv_bfloat16 g_A2[MPAD * KA];
__device__ __align__(256) __nv_bfloat16 g_Z2a[KA * COLS];   // z (GEMM1 input)
__device__ __align__(256) __nv_bfloat16 g_Z2b[KA * COLS];   // h (GEMM2 input)

__device__ __forceinline__ float warp_sum(float v) {
#pragma unroll
    for (int o = 16; o > 0; o >>= 1) v += __shfl_xor_sync(0xffffffffu, v, o);
    return v;
}

// m16n8k16 row.col bf16 -> fp32 mma (standard PTX, works on plain sm_103)
__device__ __forceinline__ void mma16816(float* d, const uint32_t* a, const uint32_t* b,
                                         const float* c) {
    asm volatile("mma.sync.aligned.m16n8k16.row.col.f32.bf16.bf16.f32 "
                 "{%0,%1,%2,%3}, {%4,%5,%6,%7}, {%8,%9}, {%10,%11,%12,%13};"
                 : "=f"(d[0]), "=f"(d[1]), "=f"(d[2]), "=f"(d[3])
                 : "r"(a[0]), "r"(a[1]), "r"(a[2]), "r"(a[3]),
                   "r"(b[0]), "r"(b[1]),
                   "f"(c[0]), "f"(c[1]), "f"(c[2]), "f"(c[3]));
}

// Split-bf16 store into k-major [640 x 4096]: hi at row n, lo at row n+320
__device__ __forceinline__ void split_store2(__nv_bfloat16* base, int n, int c,
                                             float v0, float v1) {
    const __nv_bfloat16 h0 = __float2bfloat16(v0);
    const __nv_bfloat16 h1 = __float2bfloat16(v1);
    const __nv_bfloat16 l0 = __float2bfloat16(v0 - __bfloat162float(h0));
    const __nv_bfloat16 l1 = __float2bfloat16(v1 - __bfloat162float(h1));
    __nv_bfloat162 hh; hh.x = h0; hh.y = h1;
    __nv_bfloat162 ll; ll.x = l0; ll.y = l1;
    *(__nv_bfloat162*)(base + (size_t)n * COLS + c)          = hh;
    *(__nv_bfloat162*)(base + (size_t)(n + KSEG) * COLS + c) = ll;
}

// ---------------------------------------------------------------------------
// Build A2 = [A_hi | A_lo]  (384 x 640 bf16), once per launch
// ---------------------------------------------------------------------------
__global__ void __launch_bounds__(256) prepA_kernel(const float* __restrict__ A,
                                                    __nv_bfloat16* __restrict__ A2) {
    const int idx = blockIdx.x * 256 + threadIdx.x;
    if (idx >= MPAD * KA) return;
    const int m = idx / KA, k = idx % KA;
    const int kk = (k >= KSEG) ? k - KSEG : k;
    const float v = (m < NN && kk < NN) ? A[m * NN + kk] : 0.f;
    const __nv_bfloat16 hi = __float2bfloat16(v);
    A2[idx] = (k >= KSEG) ? __float2bfloat16(v - __bfloat162float(hi)) : hi;
}

// ---------------------------------------------------------------------------
// mma.sync GEMM: Out[m,c] (m<307) = split-bf16 A @ Z ; grid (64, 3) x 256thr
// Warp grid 4(m) x 2(n); warp tile 32x32; frags 2x4 of m16n8k16.
// ---------------------------------------------------------------------------
__global__ void __launch_bounds__(256) gemm_tc_kernel(const __nv_bfloat16* __restrict__ A2,
                                                      const __nv_bfloat16* __restrict__ Z2,
                                                      float* __restrict__ Out) {
    __shared__ __nv_bfloat16 smA[MT * PA];   // 128 x 72  (18432 B)
    __shared__ __nv_bfloat16 smB[NT * PB];   //  64 x 76  ( 9728 B)

    const int tid = threadIdx.x;
    const int lane = tid & 31, wid = tid >> 5;
    const int mw = wid & 3, nw = wid >> 2;
    const int g = lane >> 2, q = lane & 3;

    const int m0 = blockIdx.y * MT;
    const int c0 = blockIdx.x * NT;
    const __nv_bfloat16* Ag = A2 + (size_t)m0 * KA;
    const __nv_bfloat16* Bg = Z2 + c0;

    float acc[2][4][4];
#pragma unroll
    for (int fm = 0; fm < 2; fm++)
#pragma unroll
        for (int fn = 0; fn < 4; fn++)
#pragma unroll
            for (int j = 0; j < 4; j++) acc[fm][fn][j] = 0.f;

    for (int ch = 0; ch < NCH; ch++) {
        const int seg = ch / 5;
        const int kk0 = (ch % 5) * KC;
        const int a_off = kk0 + ((seg == 1) ? KSEG : 0);
        const int b_off = kk0 + ((seg == 2) ? KSEG : 0);

        // Stage A tile: 128 rows x 64 bf16, row-contiguous -> STS.128
#pragma unroll
        for (int i = 0; i < 4; i++) {
            const int idx = tid + i * 256;        // 0..1023
            const int row = idx >> 3;
            const int qq = idx & 7;
            const uint4 v = *(const uint4*)(Ag + (size_t)row * KA + a_off + qq * 8);
            *(uint4*)(smA + row * PA + qq * 8) = v;   // 144B pitch, 16B aligned
        }
        // Stage B transposed: smB[n][k]; per thread pack 2 k-values -> 4B store
#pragma unroll
        for (int i = 0; i < 8; i++) {
            const int idx = tid + i * 256;        // 0..2047
            const int kp = idx >> 6;              // 0..31
            const int c = idx & 63;               // 0..63
            __nv_bfloat162 p;
            p.x = Bg[(size_t)(b_off + 2 * kp) * COLS + c];
            p.y = Bg[(size_t)(b_off + 2 * kp + 1) * COLS + c];
            *(__nv_bfloat162*)(smB + c * PB + 2 * kp) = p;
        }
        __syncthreads();

#pragma unroll
        for (int ks = 0; ks < 4; ks++) {
            const int kk = ks * 16;
            uint32_t af[2][4], bf[4][2];
#pragma unroll
            for (int fm = 0; fm < 2; fm++) {
                const __nv_bfloat16* ap = smA + (mw * 32 + fm * 16 + g) * PA + kk + q * 2;
                af[fm][0] = *(const uint32_t*)(ap);
                af[fm][1] = *(const uint32_t*)(ap + 8 * PA);
                af[fm][2] = *(const uint32_t*)(ap + 8);
                af[fm][3] = *(const uint32_t*)(ap + 8 * PA + 8);
            }
#pragma unroll
            for (int fn = 0; fn < 4; fn++) {
                const __nv_bfloat16* bp = smB + (nw * 32 + fn * 8 + g) * PB + kk + q * 2;
                bf[fn][0] = *(const uint32_t*)(bp);
                bf[fn][1] = *(const uint32_t*)(bp + 8);
            }
#pragma unroll
            for (int fm = 0; fm < 2; fm++)
#pragma unroll
                for (int fn = 0; fn < 4; fn++)
                    mma16816(acc[fm][fn], af[fm], bf[fn], acc[fm][fn]);
        }
        __syncthreads();
    }

    // Epilogue: D[g][n0..n0+1] / D[g+8][...] per frag -> float2 stores
#pragma unroll
    for (int fm = 0; fm < 2; fm++) {
        const int r1 = m0 + mw * 32 + fm * 16 + g;
        const int r2 = r1 + 8;
#pragma unroll
        for (int fn = 0; fn < 4; fn++) {
            const int c = c0 + nw * 32 + fn * 8 + q * 2;
            if (r1 < NN)
                *(float2*)(Out + (size_t)r1 * COLS + c) = make_float2(acc[fm][fn][0], acc[fm][fn][1]);
            if (r2 < NN)
                *(float2*)(Out + (size_t)r2 * COLS + c) = make_float2(acc[fm][fn][2], acc[fm][fn][3]);
        }
    }
}

// ---------------------------------------------------------------------------
// gc: h = tanh(b1 @ W1) -> split-bf16 into Z2b only
// ---------------------------------------------------------------------------
__global__ void __launch_bounds__(256) gc_kernel(const float* __restrict__ in,
                                                 const float* __restrict__ W,
                                                 __nv_bfloat16* __restrict__ Z2b) {
    __shared__ float Ws[4096];
    __shared__ float rows[8][64];
    const int tid = threadIdx.x;
    for (int i = tid; i < 4096; i += 256) Ws[i] = W[i];
    __syncthreads();
    const int lane = tid & 31, rl = tid >> 5;
    const int h0 = 2 * lane, h1 = h0 + 1;
    for (int it = 0; it < 4; it++) {
        const int r = blockIdx.x * 32 + it * 8 + rl;
        const int n = r >> 6, b = r & 63;
        __syncwarp();
        const float2 rv = *reinterpret_cast<const float2*>(in + (size_t)r * HH + h0);
        rows[rl][h0] = rv.x; rows[rl][h1] = rv.y;
        __syncwarp();
        float a0 = 0.f, a1 = 0.f;
#pragma unroll
        for (int k = 0; k < 64; k++) {
            const float c = rows[rl][k];
            const float2 w = *reinterpret_cast<const float2*>(&Ws[k * 64 + h0]);
            a0 += c * w.x; a1 += c * w.y;
        }
        split_store2(Z2b, n, (b << 6) + h0, tanhf(a0), tanhf(a1));
    }
}

// ---------------------------------------------------------------------------
// c1: z = 2z + LN(tanh(b1 @ W2)) * g + b
// ---------------------------------------------------------------------------
__global__ void __launch_bounds__(256) c1_kernel(const float* __restrict__ AH,
                                                 const float* __restrict__ W2,
                                                 const float* __restrict__ ln_g,
                                                 const float* __restrict__ ln_b,
                                                 float* __restrict__ z) {
    __shared__ float Ws[4096];
    __shared__ float rows[8][64];
    __shared__ float gs[64], bs[64];
    const int tid = threadIdx.x;
    for (int i = tid; i < 4096; i += 256) Ws[i] = W2[i];
    if (tid < 64) { gs[tid] = ln_g[tid]; bs[tid] = ln_b[tid]; }
    __syncthreads();
    const int lane = tid & 31, rl = tid >> 5;
    const int h0 = 2 * lane, h1 = h0 + 1;
    for (int it = 0; it < 4; it++) {
        const int r = blockIdx.x * 32 + it * 8 + rl;
        __syncwarp();
        const float2 rv = *reinterpret_cast<const float2*>(AH + (size_t)r * HH + h0);
        rows[rl][h0] = rv.x; rows[rl][h1] = rv.y;
        __syncwarp();
        float a0 = 0.f, a1 = 0.f;
#pragma unroll
        for (int k = 0; k < 64; k++) {
            const float c = rows[rl][k];
            const float2 w = *reinterpret_cast<const float2*>(&Ws[k * 64 + h0]);
            a0 += c * w.x; a1 += c * w.y;
        }
        const float ha = tanhf(a0), hb = tanhf(a1);
        const float mu = warp_sum(ha + hb) * (1.f / 64.f);
        const float da = ha - mu, db = hb - mu;
        const float var = warp_sum(da * da + db * db) * (1.f / 64.f);
        const float rstd = rsqrtf(var + 1e-5f);
        const float d0 = da * rstd * gs[h0] + bs[h0];
        const float d1 = db * rstd * gs[h1] + bs[h1];
        float2* zp = reinterpret_cast<float2*>(z + (size_t)r * HH + h0);
        const float2 zv = *zp;
        *zp = make_float2(2.f * zv.x + d0, 2.f * zv.y + d1);
    }
}

// ---------------------------------------------------------------------------
// c2: gate/update/pred; emits z as split-bf16 into Z2a
// ---------------------------------------------------------------------------
__global__ void __launch_bounds__(256) c2_kernel(const float* __restrict__ x_seq,
                                                 const float* __restrict__ obs_mask,
                                                 const float* __restrict__ W_obs,
                                                 const float* __restrict__ b_obs,
                                                 const float* __restrict__ W_gate,
                                                 const float* __restrict__ b_gate,
                                                 const float* __restrict__ W_dec,
                                                 const float* __restrict__ b_dec,
                                                 float* __restrict__ z,
                                                 __nv_bfloat16* __restrict__ Z2a,
                                                 float* __restrict__ preds,
                                                 int t1) {
    __shared__ float Wg[128 * 64];
    __shared__ float cat[8][128];
    __shared__ float Wo[192], bo[64], bg[64], wd[64];
    const int tid = threadIdx.x;
    for (int i = tid; i < 8192; i += 256) Wg[i] = W_gate[i];
    if (tid < 192) Wo[tid] = W_obs[tid];
    if (tid < 64) { bo[tid] = b_obs[tid]; bg[tid] = b_gate[tid]; wd[tid] = W_dec[tid]; }
    __syncthreads();
    const int lane = tid & 31, rl = tid >> 5;
    const int h0 = 2 * lane, h1 = h0 + 1;
    const float bdec = b_dec[0];
    for (int it = 0; it < 4; it++) {
        const int r = blockIdx.x * 32 + it * 8 + rl;
        const int n = r >> 6, b = r & 63;
        const float2 zv = *reinterpret_cast<const float2*>(z + (size_t)r * HH + h0);
        const float* x = x_seq + ((size_t)(b * NN + n) * TT + t1) * FF;
        const float x0 = x[0], x1 = x[1], x2 = x[2];
        const float zo0 = bo[h0] + x0 * Wo[h0] + x1 * Wo[64 + h0] + x2 * Wo[128 + h0];
        const float zo1 = bo[h1] + x0 * Wo[h1] + x1 * Wo[64 + h1] + x2 * Wo[128 + h1];
        __syncwarp();
        cat[rl][h0] = zv.x; cat[rl][h1] = zv.y;
        cat[rl][64 + h0] = zo0; cat[rl][64 + h1] = zo1;
        __syncwarp();
        float a0 = bg[h0], a1 = bg[h1];
#pragma unroll
        for (int k = 0; k < 128; k++) {
            const float c = cat[rl][k];
            const float2 w = *reinterpret_cast<const float2*>(&Wg[k * 64 + h0]);
            a0 += c * w.x; a1 += c * w.y;
        }
        const float g0 = 1.f / (1.f + __expf(-a0));
        const float g1 = 1.f / (1.f + __expf(-a1));
        const float m = obs_mask[b * NN + n];
        const float zf0 = zv.x + g0 * (zo0 - zv.x) * m;
        const float zf1 = zv.y + g1 * (zo1 - zv.y) * m;
        *reinterpret_cast<float2*>(z + (size_t)r * HH + h0) = make_float2(zf0, zf1);
        split_store2(Z2a, n, (b << 6) + h0, zf0, zf1);
        const float p = warp_sum(zf0 * wd[h0] + zf1 * wd[h1]);
        if (lane == 0) preds[(size_t)(b * NN + n) * TT + t1] = p + bdec;
    }
}

// ---------------------------------------------------------------------------
// Encoder: z0 + preds[...,0]; seeds Z2a
// ---------------------------------------------------------------------------
__global__ void __launch_bounds__(256) enc_kernel(const float* __restrict__ x_seq,
                                                  const float* __restrict__ W_enc,
                                                  const float* __restrict__ b_enc,
                                                  const float* __restrict__ W_dec,
                                                  const float* __restrict__ b_dec,
                                                  float* __restrict__ z,
                                                  __nv_bfloat16* __restrict__ Z2a,
                                                  float* __restrict__ preds) {
    const int tid = threadIdx.x;
    const int lane = tid & 31;
    const int r = blockIdx.x * 8 + (tid >> 5);
    const int n = r >> 6, b = r & 63;
    const float* x = x_seq + (size_t)(b * NN + n) * TT * FF;  // t = 0
    const float x0 = x[0], x1 = x[1], x2 = x[2];
    const int h0 = 2 * lane, h1 = h0 + 1;
    const float za = b_enc[h0] + x0 * W_enc[h0] + x1 * W_enc[64 + h0] + x2 * W_enc[128 + h0];
    const float zb = b_enc[h1] + x0 * W_enc[h1] + x1 * W_enc[64 + h1] + x2 * W_enc[128 + h1];
    *reinterpret_cast<float2*>(z + (size_t)r * HH + h0) = make_float2(za, zb);
    split_store2(Z2a, n, (b << 6) + h0, za, zb);
    const float p = warp_sum(za * W_dec[h0] + zb * W_dec[h1]);
    if (lane == 0) preds[(size_t)(b * NN + n) * TT + 0] = p + b_dec[0];
}

// ---------------------------------------------------------------------------
extern "C" void kernel_launch(void* const* d_in, const int* in_sizes, int n_in,
                              void* d_out, int out_size) {
    const float* x_seq   = (const float*)d_in[0];
    const float* obs_mask= (const float*)d_in[1];
    const float* A       = (const float*)d_in[2];
    const float* W_enc   = (const float*)d_in[3];
    const float* b_enc   = (const float*)d_in[4];
    const float* W_gc1   = (const float*)d_in[5];
    const float* W_gc2   = (const float*)d_in[6];
    const float* ln_g    = (const float*)d_in[7];
    const float* ln_b    = (const float*)d_in[8];
    const float* W_obs   = (const float*)d_in[9];
    const float* b_obs   = (const float*)d_in[10];
    const float* W_gate  = (const float*)d_in[11];
    const float* b_gate  = (const float*)d_in[12];
    const float* W_dec   = (const float*)d_in[13];
    const float* b_dec   = (const float*)d_in[14];
    float* preds = (float*)d_out;

    float *z, *b1;
    __nv_bfloat16 *a2, *z2a, *z2b;
    cudaGetSymbolAddress((void**)&z,   g_z);
    cudaGetSymbolAddress((void**)&b1,  g_b1);
    cudaGetSymbolAddress((void**)&a2,  g_A2);
    cudaGetSymbolAddress((void**)&z2a, g_Z2a);
    cudaGetSymbolAddress((void**)&z2b, g_Z2b);

    prepA_kernel<<<(MPAD * KA + 255) / 256, 256>>>(A, a2);
    enc_kernel<<<ROWS / 8, 256>>>(x_seq, W_enc, b_enc, W_dec, b_dec, z, z2a, preds);

    const dim3 ggrid(COLS / NT, MPAD / MT);   // 64 x 3
    for (int t = 0; t < TT - 1; t++) {
        gemm_tc_kernel<<<ggrid, 256>>>(a2, z2a, b1);
        gc_kernel<<<ROWS / 32, 256>>>(b1, W_gc1, z2b);
        gemm_tc_kernel<<<ggrid, 256>>>(a2, z2b, b1);
        c1_kernel<<<ROWS / 32, 256>>>(b1, W_gc2, ln_g, ln_b, z);
        c2_kernel<<<ROWS / 32, 256>>>(x_seq, obs_mask, W_obs, b_obs,
                                      W_gate, b_gate, W_dec, b_dec,
                                      z, z2a, preds, t + 1);
    }
}

// round 15
// speedup vs baseline: 1.2239x; 1.0779x over previous
#include <cuda_runtime.h>
#include <cuda_bf16.h>
#include <stdint.h>
#include <math.h>

// Problem constants
#define BB 64
#define NN 307
#define TT 64
#define FF 3
#define HH 64
#define ROWS (NN * BB)          // 19648
#define COLS (BB * HH)          // 4096

// Split-bf16 A-GEMM: A2 = [A_hi | A_lo] (384x640), Z2 = [Z_hi ; Z_lo] (640x4096 k-major)
#define KSEG 320
#define KA   640
#define MPAD 384
#define KC   64
#define NCH  15
#define MT   128
#define NT   64
#define PA   72      // smA pitch (bf16) = 144B
#define PB   76      // smB pitch (bf16)
#define PTF_T 66     // smT pitch (fp32) -> conflict-free scalar row reads
#define PTF_W 68     // smW pitch (fp32) -> 16B-aligned float4 reads

// Dynamic smem union:
//  phase1: smA[0..18432) + smB[18432..28160)
//  phase2: smT fp32 [0..33792) + smW fp32 [33792..51200)
#define OFF_SMB   (MT * PA * 2)        // 18432
#define OFF_SMW_F (MT * PTF_T * 4)     // 33792
#define DSMEM     (OFF_SMW_F + 64 * PTF_W * 4)   // 51200

// Persistent scratch (__device__ globals; zero-init -> padding rows stay 0 forever)
__device__ __align__(256) float         g_z   [ROWS * HH];
__device__ __align__(256) __nv_bfloat16 g_A2  [MPAD * KA];
__device__ __align__(256) __nv_bfloat16 g_Z2a [KA * COLS];   // z (F1 input)
__device__ __align__(256) __nv_bfloat16 g_Z2b [KA * COLS];   // h (F2 input)
__device__ __align__(256) float         g_wcomb[3 * 64];     // W_obs @ Wg_bot
__device__ __align__(256) float         g_bgc  [64];         // b_gate + b_obs @ Wg_bot

__device__ __forceinline__ void mma16816(float* d, const uint32_t* a, const uint32_t* b,
                                         const float* c) {
    asm volatile("mma.sync.aligned.m16n8k16.row.col.f32.bf16.bf16.f32 "
                 "{%0,%1,%2,%3}, {%4,%5,%6,%7}, {%8,%9}, {%10,%11,%12,%13};"
                 : "=f"(d[0]), "=f"(d[1]), "=f"(d[2]), "=f"(d[3])
                 : "r"(a[0]), "r"(a[1]), "r"(a[2]), "r"(a[3]),
                   "r"(b[0]), "r"(b[1]),
                   "f"(c[0]), "f"(c[1]), "f"(c[2]), "f"(c[3]));
}

// Split-bf16 store into k-major [640 x 4096]: hi at row n, lo at row n+320
__device__ __forceinline__ void split_store2(__nv_bfloat16* base, int n, int c,
                                             float v0, float v1) {
    const __nv_bfloat16 h0 = __float2bfloat16(v0);
    const __nv_bfloat16 h1 = __float2bfloat16(v1);
    const __nv_bfloat16 l0 = __float2bfloat16(v0 - __bfloat162float(h0));
    const __nv_bfloat16 l1 = __float2bfloat16(v1 - __bfloat162float(h1));
    __nv_bfloat162 hh; hh.x = h0; hh.y = h1;
    __nv_bfloat162 ll; ll.x = l0; ll.y = l1;
    *(__nv_bfloat162*)(base + (size_t)n * COLS + c)          = hh;
    *(__nv_bfloat162*)(base + (size_t)(n + KSEG) * COLS + c) = ll;
}

// ---------------------------------------------------------------------------
// Main split-bf16 A-GEMM into register acc[2][4][4] (warp grid 4m x 2n)
// ---------------------------------------------------------------------------
__device__ __forceinline__ void main_gemm(const __nv_bfloat16* __restrict__ Ag,
                                          const __nv_bfloat16* __restrict__ Bg,
                                          __nv_bfloat16* smA, __nv_bfloat16* smB,
                                          int tid, int mw, int nw, int g, int q,
                                          float acc[2][4][4]) {
#pragma unroll
    for (int fm = 0; fm < 2; fm++)
#pragma unroll
        for (int fn = 0; fn < 4; fn++)
#pragma unroll
            for (int j = 0; j < 4; j++) acc[fm][fn][j] = 0.f;

    for (int ch = 0; ch < NCH; ch++) {
        const int seg = ch / 5;
        const int kk0 = (ch % 5) * KC;
        const int a_off = kk0 + ((seg == 1) ? KSEG : 0);
        const int b_off = kk0 + ((seg == 2) ? KSEG : 0);
#pragma unroll
        for (int i = 0; i < 4; i++) {
            const int idx = tid + i * 256;
            const int row = idx >> 3;
            const int qq = idx & 7;
            const uint4 v = *(const uint4*)(Ag + (size_t)row * KA + a_off + qq * 8);
            *(uint4*)(smA + row * PA + qq * 8) = v;
        }
#pragma unroll
        for (int i = 0; i < 8; i++) {
            const int idx = tid + i * 256;
            const int kp = idx >> 6;
            const int c = idx & 63;
            __nv_bfloat162 p;
            p.x = Bg[(size_t)(b_off + 2 * kp) * COLS + c];
            p.y = Bg[(size_t)(b_off + 2 * kp + 1) * COLS + c];
            *(__nv_bfloat162*)(smB + c * PB + 2 * kp) = p;
        }
        __syncthreads();
#pragma unroll
        for (int ks = 0; ks < 4; ks++) {
            const int kk = ks * 16;
            uint32_t af[2][4], bf[4][2];
#pragma unroll
            for (int fm = 0; fm < 2; fm++) {
                const __nv_bfloat16* ap = smA + (mw * 32 + fm * 16 + g) * PA + kk + q * 2;
                af[fm][0] = *(const uint32_t*)(ap);
                af[fm][1] = *(const uint32_t*)(ap + 8 * PA);
                af[fm][2] = *(const uint32_t*)(ap + 8);
                af[fm][3] = *(const uint32_t*)(ap + 8 * PA + 8);
            }
#pragma unroll
            for (int fn = 0; fn < 4; fn++) {
                const __nv_bfloat16* bp = smB + (nw * 32 + fn * 8 + g) * PB + kk + q * 2;
                bf[fn][0] = *(const uint32_t*)(bp);
                bf[fn][1] = *(const uint32_t*)(bp + 8);
            }
#pragma unroll
            for (int fm = 0; fm < 2; fm++)
#pragma unroll
                for (int fn = 0; fn < 4; fn++)
                    mma16816(acc[fm][fn], af[fm], bf[fn], acc[fm][fn]);
        }
        __syncthreads();
    }
}

// Stage acc tile (128x64) into smT as FP32
__device__ __forceinline__ void stage_acc_f32(float* smT, const float acc[2][4][4],
                                              int mw, int nw, int g, int q) {
#pragma unroll
    for (int fm = 0; fm < 2; fm++) {
        const int r1 = mw * 32 + fm * 16 + g;
#pragma unroll
        for (int fn = 0; fn < 4; fn++) {
            const int col = nw * 32 + fn * 8 + 2 * q;
            *(float2*)(smT + r1 * PTF_T + col) = make_float2(acc[fm][fn][0], acc[fm][fn][1]);
            *(float2*)(smT + (r1 + 8) * PTF_T + col) = make_float2(acc[fm][fn][2], acc[fm][fn][3]);
        }
    }
}

// Stage a [64x64] fp32 weight (k-major, W[k][j]) into smW (pitch PTF_W)
__device__ __forceinline__ void stage_w_f32(float* smW, const float* __restrict__ W, int tid) {
#pragma unroll
    for (int i = tid; i < 4096; i += 256)
        smW[(i >> 6) * PTF_W + (i & 63)] = W[i];
}

// fp32 small matmul: v[4][8] = smT(rows r0..r0+3) @ smW ; thread cols cg*8..cg*8+7
__device__ __forceinline__ void small_f32(const float* smT, const float* smW,
                                          int r0, int cg, float v[4][8]) {
#pragma unroll
    for (int i = 0; i < 4; i++)
#pragma unroll
        for (int j = 0; j < 8; j++) v[i][j] = 0.f;
    for (int k = 0; k < 64; k++) {
        const float4 wa = *(const float4*)(smW + k * PTF_W + cg * 8);
        const float4 wb = *(const float4*)(smW + k * PTF_W + cg * 8 + 4);
#pragma unroll
        for (int i = 0; i < 4; i++) {
            const float tv = smT[(r0 + i) * PTF_T + k];
            v[i][0] += tv * wa.x; v[i][1] += tv * wa.y;
            v[i][2] += tv * wa.z; v[i][3] += tv * wa.w;
            v[i][4] += tv * wb.x; v[i][5] += tv * wb.y;
            v[i][6] += tv * wb.z; v[i][7] += tv * wb.w;
        }
    }
}

__device__ __forceinline__ float red8(float v) {
    v += __shfl_xor_sync(0xffffffffu, v, 1);
    v += __shfl_xor_sync(0xffffffffu, v, 2);
    v += __shfl_xor_sync(0xffffffffu, v, 4);
    return v;
}

// ---------------------------------------------------------------------------
// F1: AZ = A@Z2a (split-bf16 mma) ; h = tanh(AZ @ W1) (fp32) -> Z2b
// ---------------------------------------------------------------------------
__global__ void __launch_bounds__(256) stepA_kernel(const __nv_bfloat16* __restrict__ A2,
                                                    const __nv_bfloat16* __restrict__ Z2a,
                                                    const float* __restrict__ W1,
                                                    __nv_bfloat16* __restrict__ Z2b) {
    extern __shared__ char dsm[];
    __nv_bfloat16* smA = (__nv_bfloat16*)dsm;
    __nv_bfloat16* smB = (__nv_bfloat16*)(dsm + OFF_SMB);
    float* smT = (float*)dsm;
    float* smW = (float*)(dsm + OFF_SMW_F);

    const int tid = threadIdx.x;
    const int lane = tid & 31, wid = tid >> 5;
    const int mw = wid & 3, nw = wid >> 2;
    const int g = lane >> 2, q = lane & 3;
    const int bb = blockIdx.x, m0 = blockIdx.y * MT;

    float acc[2][4][4];
    main_gemm(A2 + (size_t)m0 * KA, Z2a + bb * 64, smA, smB, tid, mw, nw, g, q, acc);

    stage_acc_f32(smT, acc, mw, nw, g, q);
    stage_w_f32(smW, W1, tid);
    __syncthreads();

    const int cg = tid & 7, r0 = (tid >> 3) * 4;
    float v[4][8];
    small_f32(smT, smW, r0, cg, v);

#pragma unroll
    for (int i = 0; i < 4; i++) {
        const int n = m0 + r0 + i;
        if (n < NN) {
#pragma unroll
            for (int j = 0; j < 8; j += 2)
                split_store2(Z2b, n, (bb << 6) + cg * 8 + j,
                             tanhf(v[i][j]), tanhf(v[i][j + 1]));
        }
    }
}

// ---------------------------------------------------------------------------
// F2: AH = A@Z2b ; t = tanh(AH @ W2) ; delta = LN(t) ; z1 = 2z + delta ;
//     gate = sigmoid(z1@Wg_top + x@Wcomb + bgc) ; z = z1 + gate*(zo-z1)*mask
//     -> g_z, Z2a, preds.   All pointwise matmuls in fp32.
// ---------------------------------------------------------------------------
__global__ void __launch_bounds__(256) stepB_kernel(const __nv_bfloat16* __restrict__ A2,
                                                    const __nv_bfloat16* __restrict__ Z2b,
                                                    const float* __restrict__ W2,
                                                    const float* __restrict__ Wg,     // full [128][64]; rows 0..63 used here
                                                    const float* __restrict__ ln_g,
                                                    const float* __restrict__ ln_b,
                                                    const float* __restrict__ W_obs,
                                                    const float* __restrict__ b_obs,
                                                    const float* __restrict__ wcomb,
                                                    const float* __restrict__ bgc,
                                                    const float* __restrict__ W_dec,
                                                    const float* __restrict__ b_dec,
                                                    const float* __restrict__ x_seq,
                                                    const float* __restrict__ obs_mask,
                                                    float* __restrict__ z,
                                                    __nv_bfloat16* __restrict__ Z2a,
                                                    float* __restrict__ preds,
                                                    int t1) {
    extern __shared__ char dsm[];
    __nv_bfloat16* smA = (__nv_bfloat16*)dsm;
    __nv_bfloat16* smB = (__nv_bfloat16*)(dsm + OFF_SMB);
    float* smT = (float*)dsm;
    float* smW = (float*)(dsm + OFF_SMW_F);
    __shared__ float cs_lng[64], cs_lnb[64], cs_wo[192], cs_bo[64];
    __shared__ float cs_bgc[64], cs_wc[192], cs_wd[64];

    const int tid = threadIdx.x;
    const int lane = tid & 31, wid = tid >> 5;
    const int mw = wid & 3, nw = wid >> 2;
    const int g = lane >> 2, q = lane & 3;
    const int bb = blockIdx.x, m0 = blockIdx.y * MT;

    if (tid < 64) {
        cs_lng[tid] = ln_g[tid]; cs_lnb[tid] = ln_b[tid];
        cs_bo[tid] = b_obs[tid]; cs_bgc[tid] = bgc[tid]; cs_wd[tid] = W_dec[tid];
    }
    if (tid < 192) { cs_wo[tid] = W_obs[tid]; cs_wc[tid] = wcomb[tid]; }
    // covered by first __syncthreads inside main_gemm

    float acc[2][4][4];
    main_gemm(A2 + (size_t)m0 * KA, Z2b + bb * 64, smA, smB, tid, mw, nw, g, q, acc);

    stage_acc_f32(smT, acc, mw, nw, g, q);
    stage_w_f32(smW, W2, tid);
    __syncthreads();

    const int cg = tid & 7, r0 = (tid >> 3) * 4;
    float v[4][8];
    small_f32(smT, smW, r0, cg, v);      // AH @ W2

    // tanh
#pragma unroll
    for (int i = 0; i < 4; i++)
#pragma unroll
        for (int j = 0; j < 8; j++) v[i][j] = tanhf(v[i][j]);

    // LayerNorm per row (reduce across the 8 cg lanes)
    float mu[4], rs[4];
#pragma unroll
    for (int i = 0; i < 4; i++) {
        float s = 0.f;
#pragma unroll
        for (int j = 0; j < 8; j++) s += v[i][j];
        mu[i] = red8(s) * (1.f / 64.f);
        float vr = 0.f;
#pragma unroll
        for (int j = 0; j < 8; j++) { const float d = v[i][j] - mu[i]; vr += d * d; }
        rs[i] = rsqrtf(red8(vr) * (1.f / 64.f) + 1e-5f);
    }

    // z1 = 2z + delta
#pragma unroll
    for (int i = 0; i < 4; i++) {
        const int n = m0 + r0 + i;
        float zr[8] = {0.f, 0.f, 0.f, 0.f, 0.f, 0.f, 0.f, 0.f};
        if (n < NN) {
            const float* zp = z + (((size_t)(n << 6) + bb) << 6) + cg * 8;
            const float4 za = *(const float4*)(zp);
            const float4 zb2 = *(const float4*)(zp + 4);
            zr[0] = za.x; zr[1] = za.y; zr[2] = za.z; zr[3] = za.w;
            zr[4] = zb2.x; zr[5] = zb2.y; zr[6] = zb2.z; zr[7] = zb2.w;
        }
#pragma unroll
        for (int j = 0; j < 8; j++) {
            const int c = cg * 8 + j;
            v[i][j] = 2.f * zr[j] + (v[i][j] - mu[i]) * rs[i] * cs_lng[c] + cs_lnb[c];
        }
    }

    // gate logit matmul in fp32: stage z1, stage Wg_top, multiply
    __syncthreads();
#pragma unroll
    for (int i = 0; i < 4; i++)
#pragma unroll
        for (int j = 0; j < 8; j += 2)
            *(float2*)(smT + (r0 + i) * PTF_T + cg * 8 + j) = make_float2(v[i][j], v[i][j + 1]);
    stage_w_f32(smW, Wg, tid);   // rows 0..63 of W_gate (z1 part)
    __syncthreads();

    float lg[4][8];
    small_f32(smT, smW, r0, cg, lg);

    const float bdec = b_dec[0];
#pragma unroll
    for (int i = 0; i < 4; i++) {
        const int n = m0 + r0 + i;
        float x0 = 0.f, x1 = 0.f, x2 = 0.f, m = 0.f;
        if (n < NN) {
            const float* xp = x_seq + ((size_t)(bb * NN + n) * TT + t1) * FF;
            x0 = xp[0]; x1 = xp[1]; x2 = xp[2];
            m = obs_mask[bb * NN + n];
        }
        float p = 0.f;
#pragma unroll
        for (int j = 0; j < 8; j++) {
            const int c = cg * 8 + j;
            const float lgv = lg[i][j] + x0 * cs_wc[c] + x1 * cs_wc[64 + c]
                            + x2 * cs_wc[128 + c] + cs_bgc[c];
            const float gate = 1.f / (1.f + __expf(-lgv));
            const float zo = cs_bo[c] + x0 * cs_wo[c] + x1 * cs_wo[64 + c]
                           + x2 * cs_wo[128 + c];
            const float z1v = v[i][j];
            const float zf = z1v + gate * (zo - z1v) * m;
            v[i][j] = zf;
            p += zf * cs_wd[c];
        }
        if (n < NN) {
            float* zp = z + (((size_t)(n << 6) + bb) << 6) + cg * 8;
            *(float4*)(zp)     = make_float4(v[i][0], v[i][1], v[i][2], v[i][3]);
            *(float4*)(zp + 4) = make_float4(v[i][4], v[i][5], v[i][6], v[i][7]);
#pragma unroll
            for (int j = 0; j < 8; j += 2)
                split_store2(Z2a, n, (bb << 6) + cg * 8 + j, v[i][j], v[i][j + 1]);
        }
        p = red8(p);
        if (cg == 0 && n < NN) preds[(size_t)(bb * NN + n) * TT + t1] = p + bdec;
    }
}

// ---------------------------------------------------------------------------
// prepA: A2 = [A_hi | A_lo] (384 x 640 bf16)
// ---------------------------------------------------------------------------
__global__ void __launch_bounds__(256) prepA_kernel(const float* __restrict__ A,
                                                    __nv_bfloat16* __restrict__ A2) {
    const int idx = blockIdx.x * 256 + threadIdx.x;
    if (idx >= MPAD * KA) return;
    const int m = idx / KA, k = idx % KA;
    const int kk = (k >= KSEG) ? k - KSEG : k;
    const float v = (m < NN && kk < NN) ? A[m * NN + kk] : 0.f;
    const __nv_bfloat16 hi = __float2bfloat16(v);
    A2[idx] = (k >= KSEG) ? __float2bfloat16(v - __bfloat162float(hi)) : hi;
}

// ---------------------------------------------------------------------------
// prepW: Wcomb = Wo @ Wg_bot ; bgc = bg + bo @ Wg_bot  (all fp32)
// ---------------------------------------------------------------------------
__global__ void prepW_kernel(const float* __restrict__ Wg,
                             const float* __restrict__ Wo,
                             const float* __restrict__ bo,
                             const float* __restrict__ bg,
                             float* __restrict__ wcomb,
                             float* __restrict__ bgc) {
    const int j = threadIdx.x;
    if (j >= 64) return;
    float s0 = 0.f, s1 = 0.f, s2 = 0.f, sb = 0.f;
    for (int h = 0; h < 64; h++) {
        const float wg = Wg[(64 + h) * 64 + j];
        s0 += Wo[h] * wg;
        s1 += Wo[64 + h] * wg;
        s2 += Wo[128 + h] * wg;
        sb += bo[h] * wg;
    }
    wcomb[j] = s0; wcomb[64 + j] = s1; wcomb[128 + j] = s2;
    bgc[j] = bg[j] + sb;
}

// ---------------------------------------------------------------------------
// Encoder: z0 + preds[...,0]; seeds Z2a
// ---------------------------------------------------------------------------
__device__ __forceinline__ float warp_sum(float v) {
#pragma unroll
    for (int o = 16; o > 0; o >>= 1) v += __shfl_xor_sync(0xffffffffu, v, o);
    return v;
}

__global__ void __launch_bounds__(256) enc_kernel(const float* __restrict__ x_seq,
                                                  const float* __restrict__ W_enc,
                                                  const float* __restrict__ b_enc,
                                                  const float* __restrict__ W_dec,
                                                  const float* __restrict__ b_dec,
                                                  float* __restrict__ z,
                                                  __nv_bfloat16* __restrict__ Z2a,
                                                  float* __restrict__ preds) {
    const int tid = threadIdx.x;
    const int lane = tid & 31;
    const int r = blockIdx.x * 8 + (tid >> 5);
    const int n = r >> 6, b = r & 63;
    const float* x = x_seq + (size_t)(b * NN + n) * TT * FF;  // t = 0
    const float x0 = x[0], x1 = x[1], x2 = x[2];
    const int h0 = 2 * lane, h1 = h0 + 1;
    const float za = b_enc[h0] + x0 * W_enc[h0] + x1 * W_enc[64 + h0] + x2 * W_enc[128 + h0];
    const float zb = b_enc[h1] + x0 * W_enc[h1] + x1 * W_enc[64 + h1] + x2 * W_enc[128 + h1];
    *reinterpret_cast<float2*>(z + (size_t)r * HH + h0) = make_float2(za, zb);
    split_store2(Z2a, n, (b << 6) + h0, za, zb);
    const float p = warp_sum(za * W_dec[h0] + zb * W_dec[h1]);
    if (lane == 0) preds[(size_t)(b * NN + n) * TT + 0] = p + b_dec[0];
}

// ---------------------------------------------------------------------------
extern "C" void kernel_launch(void* const* d_in, const int* in_sizes, int n_in,
                              void* d_out, int out_size) {
    const float* x_seq   = (const float*)d_in[0];
    const float* obs_mask= (const float*)d_in[1];
    const float* A       = (const float*)d_in[2];
    const float* W_enc   = (const float*)d_in[3];
    const float* b_enc   = (const float*)d_in[4];
    const float* W_gc1   = (const float*)d_in[5];
    const float* W_gc2   = (const float*)d_in[6];
    const float* ln_g    = (const float*)d_in[7];
    const float* ln_b    = (const float*)d_in[8];
    const float* W_obs   = (const float*)d_in[9];
    const float* b_obs   = (const float*)d_in[10];
    const float* W_gate  = (const float*)d_in[11];
    const float* b_gate  = (const float*)d_in[12];
    const float* W_dec   = (const float*)d_in[13];
    const float* b_dec   = (const float*)d_in[14];
    float* preds = (float*)d_out;

    float *z, *wcomb, *bgc;
    __nv_bfloat16 *a2, *z2a, *z2b;
    cudaGetSymbolAddress((void**)&z,    g_z);
    cudaGetSymbolAddress((void**)&a2,   g_A2);
    cudaGetSymbolAddress((void**)&z2a,  g_Z2a);
    cudaGetSymbolAddress((void**)&z2b,  g_Z2b);
    cudaGetSymbolAddress((void**)&wcomb,g_wcomb);
    cudaGetSymbolAddress((void**)&bgc,  g_bgc);

    cudaFuncSetAttribute(stepA_kernel, cudaFuncAttributeMaxDynamicSharedMemorySize, DSMEM);
    cudaFuncSetAttribute(stepB_kernel, cudaFuncAttributeMaxDynamicSharedMemorySize, DSMEM);

    prepA_kernel<<<(MPAD * KA + 255) / 256, 256>>>(A, a2);
    prepW_kernel<<<1, 64>>>(W_gate, W_obs, b_obs, b_gate, wcomb, bgc);
    enc_kernel<<<ROWS / 8, 256>>>(x_seq, W_enc, b_enc, W_dec, b_dec, z, z2a, preds);

    const dim3 ggrid(COLS / NT, MPAD / MT);   // 64 x 3
    for (int t = 0; t < TT - 1; t++) {
        stepA_kernel<<<ggrid, 256, DSMEM>>>(a2, z2a, W_gc1, z2b);
        stepB_kernel<<<ggrid, 256, DSMEM>>>(a2, z2b, W_gc2, W_gate,
                                            ln_g, ln_b, W_obs, b_obs, wcomb, bgc,
                                            W_dec, b_dec, x_seq, obs_mask,
                                            z, z2a, preds, t + 1);
    }
}

// round 16
// speedup vs baseline: 1.4910x; 1.2183x over previous
#include <cuda_runtime.h>
#include <cuda_bf16.h>
#include <stdint.h>
#include <math.h>

// Problem constants
#define BB 64
#define NN 307
#define TT 64
#define FF 3
#define HH 64
#define ROWS (NN * BB)          // 19648
#define COLS (BB * HH)          // 4096

// Split-bf16 A-GEMM: A2 = [A_hi | A_lo] (384x640), Z2 = [Z_hi ; Z_lo] (640x4096 k-major)
#define KSEG 320
#define KA   640
#define MPAD 384
#define KC   64
#define NCH  15
#define MT   128
#define NT   64
#define PA   72      // smA pitch (bf16) = 144B -> conflict-free frag loads
#define PB   78      // smB pitch (bf16) = 156B -> 2-way max on stores
#define PTF_T 66     // smT pitch (fp32)
#define PTF_W 68     // smW pitch (fp32)

// Double-buffered phase1 smem layout (bytes):
//  smA0 [0, 18432)  smA1 [18432, 36864)  smB0 [36864, 46848)  smB1 [46848, 56832)
#define BUFA_B   (MT * PA * 2)          // 18432
#define BUFB_B   (64 * PB * 2)          // 9984
#define OFF_B0   (2 * BUFA_B)           // 36864
// phase2 union: smT fp32 [0..33792) + smW fp32 [33792..51200)
#define OFF_SMW_F (MT * PTF_T * 4)      // 33792
#define DSMEM     (OFF_B0 + 2 * BUFB_B) // 56832

// Persistent scratch (__device__ globals; zero-init -> padding rows stay 0 forever)
__device__ __align__(256) float         g_z   [ROWS * HH];
__device__ __align__(256) __nv_bfloat16 g_A2  [MPAD * KA];
__device__ __align__(256) __nv_bfloat16 g_Z2a [KA * COLS];   // z (F1 input)
__device__ __align__(256) __nv_bfloat16 g_Z2b [KA * COLS];   // h (F2 input)
__device__ __align__(256) float         g_wcomb[3 * 64];     // W_obs @ Wg_bot
__device__ __align__(256) float         g_bgc  [64];         // b_gate + b_obs @ Wg_bot

__device__ __forceinline__ void mma16816(float* d, const uint32_t* a, const uint32_t* b,
                                         const float* c) {
    asm volatile("mma.sync.aligned.m16n8k16.row.col.f32.bf16.bf16.f32 "
                 "{%0,%1,%2,%3}, {%4,%5,%6,%7}, {%8,%9}, {%10,%11,%12,%13};"
                 : "=f"(d[0]), "=f"(d[1]), "=f"(d[2]), "=f"(d[3])
                 : "r"(a[0]), "r"(a[1]), "r"(a[2]), "r"(a[3]),
                   "r"(b[0]), "r"(b[1]),
                   "f"(c[0]), "f"(c[1]), "f"(c[2]), "f"(c[3]));
}

// Split-bf16 store into k-major [640 x 4096]: hi at row n, lo at row n+320
__device__ __forceinline__ void split_store2(__nv_bfloat16* base, int n, int c,
                                             float v0, float v1) {
    const __nv_bfloat16 h0 = __float2bfloat16(v0);
    const __nv_bfloat16 h1 = __float2bfloat16(v1);
    const __nv_bfloat16 l0 = __float2bfloat16(v0 - __bfloat162float(h0));
    const __nv_bfloat16 l1 = __float2bfloat16(v1 - __bfloat162float(h1));
    __nv_bfloat162 hh; hh.x = h0; hh.y = h1;
    __nv_bfloat162 ll; ll.x = l0; ll.y = l1;
    *(__nv_bfloat162*)(base + (size_t)n * COLS + c)          = hh;
    *(__nv_bfloat162*)(base + (size_t)(n + KSEG) * COLS + c) = ll;
}

// ---------------------------------------------------------------------------
// Chunk load (gmem -> regs) and store (regs -> smem buffer)
// Per thread: A = 4x uint4 (rows tid/8 stepped by 32); B = rows 2kp,2kp+1, cgroup cq
// ---------------------------------------------------------------------------
__device__ __forceinline__ void load_chunk(const __nv_bfloat16* __restrict__ Ag,
                                           const __nv_bfloat16* __restrict__ Bg,
                                           int ch, int tid, uint4 ra[4], uint4 rb[2]) {
    const int seg = ch / 5;
    const int kk0 = (ch % 5) * KC;
    const int a_off = kk0 + ((seg == 1) ? KSEG : 0);
    const int b_off = kk0 + ((seg == 2) ? KSEG : 0);
#pragma unroll
    for (int i = 0; i < 4; i++) {
        const int idx = tid + i * 256;
        const int row = idx >> 3, qq = idx & 7;
        ra[i] = *(const uint4*)(Ag + (size_t)row * KA + a_off + qq * 8);
    }
    const int kp = tid >> 3;        // 0..31
    const int cq = tid & 7;         // 0..7
    rb[0] = *(const uint4*)(Bg + (size_t)(b_off + 2 * kp) * COLS + cq * 8);
    rb[1] = *(const uint4*)(Bg + (size_t)(b_off + 2 * kp + 1) * COLS + cq * 8);
}

__device__ __forceinline__ void store_chunk(__nv_bfloat16* smA, __nv_bfloat16* smB,
                                            int tid, const uint4 ra[4], const uint4 rb[2]) {
#pragma unroll
    for (int i = 0; i < 4; i++) {
        const int idx = tid + i * 256;
        const int row = idx >> 3, qq = idx & 7;
        *(uint4*)(smA + row * PA + qq * 8) = ra[i];
    }
    const int kp = tid >> 3;
    const int cq = tid & 7;
    const __nv_bfloat16* e0 = (const __nv_bfloat16*)&rb[0];
    const __nv_bfloat16* e1 = (const __nv_bfloat16*)&rb[1];
#pragma unroll
    for (int j = 0; j < 8; j++) {
        __nv_bfloat162 p; p.x = e0[j]; p.y = e1[j];
        *(__nv_bfloat162*)(smB + (cq * 8 + j) * PB + 2 * kp) = p;
    }
}

// ---------------------------------------------------------------------------
// Main split-bf16 A-GEMM, double-buffered (1 syncthreads per chunk)
// ---------------------------------------------------------------------------
__device__ __forceinline__ void main_gemm(const __nv_bfloat16* __restrict__ Ag,
                                          const __nv_bfloat16* __restrict__ Bg,
                                          char* dsm,
                                          int tid, int mw, int nw, int g, int q,
                                          float acc[2][4][4]) {
#pragma unroll
    for (int fm = 0; fm < 2; fm++)
#pragma unroll
        for (int fn = 0; fn < 4; fn++)
#pragma unroll
            for (int j = 0; j < 4; j++) acc[fm][fn][j] = 0.f;

    __nv_bfloat16* smAb[2] = { (__nv_bfloat16*)dsm, (__nv_bfloat16*)(dsm + BUFA_B) };
    __nv_bfloat16* smBb[2] = { (__nv_bfloat16*)(dsm + OFF_B0),
                               (__nv_bfloat16*)(dsm + OFF_B0 + BUFB_B) };

    uint4 ra[4], rb[2];
    load_chunk(Ag, Bg, 0, tid, ra, rb);
    store_chunk(smAb[0], smBb[0], tid, ra, rb);
    __syncthreads();

    for (int ch = 0; ch < NCH; ch++) {
        const int cur = ch & 1;
        const bool more = (ch + 1 < NCH);
        if (more) load_chunk(Ag, Bg, ch + 1, tid, ra, rb);   // LDGs in flight over mma

        const __nv_bfloat16* smA = smAb[cur];
        const __nv_bfloat16* smB = smBb[cur];
#pragma unroll
        for (int ks = 0; ks < 4; ks++) {
            const int kk = ks * 16;
            uint32_t af[2][4], bf[4][2];
#pragma unroll
            for (int fm = 0; fm < 2; fm++) {
                const __nv_bfloat16* ap = smA + (mw * 32 + fm * 16 + g) * PA + kk + q * 2;
                af[fm][0] = *(const uint32_t*)(ap);
                af[fm][1] = *(const uint32_t*)(ap + 8 * PA);
                af[fm][2] = *(const uint32_t*)(ap + 8);
                af[fm][3] = *(const uint32_t*)(ap + 8 * PA + 8);
            }
#pragma unroll
            for (int fn = 0; fn < 4; fn++) {
                const __nv_bfloat16* bp = smB + (nw * 32 + fn * 8 + g) * PB + kk + q * 2;
                bf[fn][0] = *(const uint32_t*)(bp);
                bf[fn][1] = *(const uint32_t*)(bp + 8);
            }
#pragma unroll
            for (int fm = 0; fm < 2; fm++)
#pragma unroll
                for (int fn = 0; fn < 4; fn++)
                    mma16816(acc[fm][fn], af[fm], bf[fn], acc[fm][fn]);
        }
        if (more) store_chunk(smAb[cur ^ 1], smBb[cur ^ 1], tid, ra, rb);
        __syncthreads();
    }
}

// Stage acc tile (128x64) into smT as FP32
__device__ __forceinline__ void stage_acc_f32(float* smT, const float acc[2][4][4],
                                              int mw, int nw, int g, int q) {
#pragma unroll
    for (int fm = 0; fm < 2; fm++) {
        const int r1 = mw * 32 + fm * 16 + g;
#pragma unroll
        for (int fn = 0; fn < 4; fn++) {
            const int col = nw * 32 + fn * 8 + 2 * q;
            *(float2*)(smT + r1 * PTF_T + col) = make_float2(acc[fm][fn][0], acc[fm][fn][1]);
            *(float2*)(smT + (r1 + 8) * PTF_T + col) = make_float2(acc[fm][fn][2], acc[fm][fn][3]);
        }
    }
}

// Stage a [64x64] fp32 weight (k-major, W[k][j]) into smW (pitch PTF_W)
__device__ __forceinline__ void stage_w_f32(float* smW, const float* __restrict__ W, int tid) {
#pragma unroll
    for (int i = tid; i < 4096; i += 256)
        smW[(i >> 6) * PTF_W + (i & 63)] = W[i];
}

// fp32 small matmul: v[4][8] = smT(rows r0..r0+3) @ smW ; thread cols cg*8..cg*8+7
__device__ __forceinline__ void small_f32(const float* smT, const float* smW,
                                          int r0, int cg, float v[4][8]) {
#pragma unroll
    for (int i = 0; i < 4; i++)
#pragma unroll
        for (int j = 0; j < 8; j++) v[i][j] = 0.f;
    for (int k = 0; k < 64; k++) {
        const float4 wa = *(const float4*)(smW + k * PTF_W + cg * 8);
        const float4 wb = *(const float4*)(smW + k * PTF_W + cg * 8 + 4);
#pragma unroll
        for (int i = 0; i < 4; i++) {
            const float tv = smT[(r0 + i) * PTF_T + k];
            v[i][0] += tv * wa.x; v[i][1] += tv * wa.y;
            v[i][2] += tv * wa.z; v[i][3] += tv * wa.w;
            v[i][4] += tv * wb.x; v[i][5] += tv * wb.y;
            v[i][6] += tv * wb.z; v[i][7] += tv * wb.w;
        }
    }
}

__device__ __forceinline__ float red8(float v) {
    v += __shfl_xor_sync(0xffffffffu, v, 1);
    v += __shfl_xor_sync(0xffffffffu, v, 2);
    v += __shfl_xor_sync(0xffffffffu, v, 4);
    return v;
}

// ---------------------------------------------------------------------------
// F1: AZ = A@Z2a (split-bf16 mma) ; h = tanh(AZ @ W1) (fp32) -> Z2b
// ---------------------------------------------------------------------------
__global__ void __launch_bounds__(256, 2) stepA_kernel(const __nv_bfloat16* __restrict__ A2,
                                                       const __nv_bfloat16* __restrict__ Z2a,
                                                       const float* __restrict__ W1,
                                                       __nv_bfloat16* __restrict__ Z2b) {
    extern __shared__ char dsm[];
    float* smT = (float*)dsm;
    float* smW = (float*)(dsm + OFF_SMW_F);

    const int tid = threadIdx.x;
    const int lane = tid & 31, wid = tid >> 5;
    const int mw = wid & 3, nw = wid >> 2;
    const int g = lane >> 2, q = lane & 3;
    const int bb = blockIdx.x, m0 = blockIdx.y * MT;

    float acc[2][4][4];
    main_gemm(A2 + (size_t)m0 * KA, Z2a + bb * 64, dsm, tid, mw, nw, g, q, acc);

    stage_acc_f32(smT, acc, mw, nw, g, q);
    stage_w_f32(smW, W1, tid);
    __syncthreads();

    const int cg = tid & 7, r0 = (tid >> 3) * 4;
    float v[4][8];
    small_f32(smT, smW, r0, cg, v);

#pragma unroll
    for (int i = 0; i < 4; i++) {
        const int n = m0 + r0 + i;
        if (n < NN) {
#pragma unroll
            for (int j = 0; j < 8; j += 2)
                split_store2(Z2b, n, (bb << 6) + cg * 8 + j,
                             tanhf(v[i][j]), tanhf(v[i][j + 1]));
        }
    }
}

// ---------------------------------------------------------------------------
// F2: AH = A@Z2b ; t = tanh(AH @ W2) ; delta = LN(t) ; z1 = 2z + delta ;
//     gate = sigmoid(z1@Wg_top + x@Wcomb + bgc) ; z = z1 + gate*(zo-z1)*mask
//     -> g_z, Z2a, preds.   All pointwise matmuls in fp32.
// ---------------------------------------------------------------------------
__global__ void __launch_bounds__(256, 2) stepB_kernel(const __nv_bfloat16* __restrict__ A2,
                                                       const __nv_bfloat16* __restrict__ Z2b,
                                                       const float* __restrict__ W2,
                                                       const float* __restrict__ Wg,
                                                       const float* __restrict__ ln_g,
                                                       const float* __restrict__ ln_b,
                                                       const float* __restrict__ W_obs,
                                                       const float* __restrict__ b_obs,
                                                       const float* __restrict__ wcomb,
                                                       const float* __restrict__ bgc,
                                                       const float* __restrict__ W_dec,
                                                       const float* __restrict__ b_dec,
                                                       const float* __restrict__ x_seq,
                                                       const float* __restrict__ obs_mask,
                                                       float* __restrict__ z,
                                                       __nv_bfloat16* __restrict__ Z2a,
                                                       float* __restrict__ preds,
                                                       int t1) {
    extern __shared__ char dsm[];
    float* smT = (float*)dsm;
    float* smW = (float*)(dsm + OFF_SMW_F);
    __shared__ float cs_lng[64], cs_lnb[64], cs_wo[192], cs_bo[64];
    __shared__ float cs_bgc[64], cs_wc[192], cs_wd[64];

    const int tid = threadIdx.x;
    const int lane = tid & 31, wid = tid >> 5;
    const int mw = wid & 3, nw = wid >> 2;
    const int g = lane >> 2, q = lane & 3;
    const int bb = blockIdx.x, m0 = blockIdx.y * MT;

    if (tid < 64) {
        cs_lng[tid] = ln_g[tid]; cs_lnb[tid] = ln_b[tid];
        cs_bo[tid] = b_obs[tid]; cs_bgc[tid] = bgc[tid]; cs_wd[tid] = W_dec[tid];
    }
    if (tid < 192) { cs_wo[tid] = W_obs[tid]; cs_wc[tid] = wcomb[tid]; }
    // covered by the first __syncthreads inside main_gemm

    float acc[2][4][4];
    main_gemm(A2 + (size_t)m0 * KA, Z2b + bb * 64, dsm, tid, mw, nw, g, q, acc);

    stage_acc_f32(smT, acc, mw, nw, g, q);
    stage_w_f32(smW, W2, tid);
    __syncthreads();

    const int cg = tid & 7, r0 = (tid >> 3) * 4;
    float v[4][8];
    small_f32(smT, smW, r0, cg, v);      // AH @ W2

    // tanh
#pragma unroll
    for (int i = 0; i < 4; i++)
#pragma unroll
        for (int j = 0; j < 8; j++) v[i][j] = tanhf(v[i][j]);

    // LayerNorm per row (reduce across the 8 cg lanes)
    float mu[4], rs[4];
#pragma unroll
    for (int i = 0; i < 4; i++) {
        float s = 0.f;
#pragma unroll
        for (int j = 0; j < 8; j++) s += v[i][j];
        mu[i] = red8(s) * (1.f / 64.f);
        float vr = 0.f;
#pragma unroll
        for (int j = 0; j < 8; j++) { const float d = v[i][j] - mu[i]; vr += d * d; }
        rs[i] = rsqrtf(red8(vr) * (1.f / 64.f) + 1e-5f);
    }

    // z1 = 2z + delta
#pragma unroll
    for (int i = 0; i < 4; i++) {
        const int n = m0 + r0 + i;
        float zr[8] = {0.f, 0.f, 0.f, 0.f, 0.f, 0.f, 0.f, 0.f};
        if (n < NN) {
            const float* zp = z + (((size_t)(n << 6) + bb) << 6) + cg * 8;
            const float4 za = *(const float4*)(zp);
            const float4 zb2 = *(const float4*)(zp + 4);
            zr[0] = za.x; zr[1] = za.y; zr[2] = za.z; zr[3] = za.w;
            zr[4] = zb2.x; zr[5] = zb2.y; zr[6] = zb2.z; zr[7] = zb2.w;
        }
#pragma unroll
        for (int j = 0; j < 8; j++) {
            const int c = cg * 8 + j;
            v[i][j] = 2.f * zr[j] + (v[i][j] - mu[i]) * rs[i] * cs_lng[c] + cs_lnb[c];
        }
    }

    // gate logit matmul in fp32: stage z1, stage Wg_top, multiply
    __syncthreads();
#pragma unroll
    for (int i = 0; i < 4; i++)
#pragma unroll
        for (int j = 0; j < 8; j += 2)
            *(float2*)(smT + (r0 + i) * PTF_T + cg * 8 + j) = make_float2(v[i][j], v[i][j + 1]);
    stage_w_f32(smW, Wg, tid);   // rows 0..63 of W_gate (z1 part)
    __syncthreads();

    float lg[4][8];
    small_f32(smT, smW, r0, cg, lg);

    const float bdec = b_dec[0];
#pragma unroll
    for (int i = 0; i < 4; i++) {
        const int n = m0 + r0 + i;
        float x0 = 0.f, x1 = 0.f, x2 = 0.f, m = 0.f;
        if (n < NN) {
            const float* xp = x_seq + ((size_t)(bb * NN + n) * TT + t1) * FF;
            x0 = xp[0]; x1 = xp[1]; x2 = xp[2];
            m = obs_mask[bb * NN + n];
        }
        float p = 0.f;
#pragma unroll
        for (int j = 0; j < 8; j++) {
            const int c = cg * 8 + j;
            const float lgv = lg[i][j] + x0 * cs_wc[c] + x1 * cs_wc[64 + c]
                            + x2 * cs_wc[128 + c] + cs_bgc[c];
            const float gate = 1.f / (1.f + __expf(-lgv));
            const float zo = cs_bo[c] + x0 * cs_wo[c] + x1 * cs_wo[64 + c]
                           + x2 * cs_wo[128 + c];
            const float z1v = v[i][j];
            const float zf = z1v + gate * (zo - z1v) * m;
            v[i][j] = zf;
            p += zf * cs_wd[c];
        }
        if (n < NN) {
            float* zp = z + (((size_t)(n << 6) + bb) << 6) + cg * 8;
            *(float4*)(zp)     = make_float4(v[i][0], v[i][1], v[i][2], v[i][3]);
            *(float4*)(zp + 4) = make_float4(v[i][4], v[i][5], v[i][6], v[i][7]);
#pragma unroll
            for (int j = 0; j < 8; j += 2)
                split_store2(Z2a, n, (bb << 6) + cg * 8 + j, v[i][j], v[i][j + 1]);
        }
        p = red8(p);
        if (cg == 0 && n < NN) preds[(size_t)(bb * NN + n) * TT + t1] = p + bdec;
    }
}

// ---------------------------------------------------------------------------
// prepA: A2 = [A_hi | A_lo] (384 x 640 bf16)
// ---------------------------------------------------------------------------
__global__ void __launch_bounds__(256) prepA_kernel(const float* __restrict__ A,
                                                    __nv_bfloat16* __restrict__ A2) {
    const int idx = blockIdx.x * 256 + threadIdx.x;
    if (idx >= MPAD * KA) return;
    const int m = idx / KA, k = idx % KA;
    const int kk = (k >= KSEG) ? k - KSEG : k;
    const float v = (m < NN && kk < NN) ? A[m * NN + kk] : 0.f;
    const __nv_bfloat16 hi = __float2bfloat16(v);
    A2[idx] = (k >= KSEG) ? __float2bfloat16(v - __bfloat162float(hi)) : hi;
}

// ---------------------------------------------------------------------------
// prepW: Wcomb = Wo @ Wg_bot ; bgc = bg + bo @ Wg_bot  (all fp32)
// ---------------------------------------------------------------------------
__global__ void prepW_kernel(const float* __restrict__ Wg,
                             const float* __restrict__ Wo,
                             const float* __restrict__ bo,
                             const float* __restrict__ bg,
                             float* __restrict__ wcomb,
                             float* __restrict__ bgc) {
    const int j = threadIdx.x;
    if (j >= 64) return;
    float s0 = 0.f, s1 = 0.f, s2 = 0.f, sb = 0.f;
    for (int h = 0; h < 64; h++) {
        const float wg = Wg[(64 + h) * 64 + j];
        s0 += Wo[h] * wg;
        s1 += Wo[64 + h] * wg;
        s2 += Wo[128 + h] * wg;
        sb += bo[h] * wg;
    }
    wcomb[j] = s0; wcomb[64 + j] = s1; wcomb[128 + j] = s2;
    bgc[j] = bg[j] + sb;
}

// ---------------------------------------------------------------------------
// Encoder: z0 + preds[...,0]; seeds Z2a
// ---------------------------------------------------------------------------
__device__ __forceinline__ float warp_sum(float v) {
#pragma unroll
    for (int o = 16; o > 0; o >>= 1) v += __shfl_xor_sync(0xffffffffu, v, o);
    return v;
}

__global__ void __launch_bounds__(256) enc_kernel(const float* __restrict__ x_seq,
                                                  const float* __restrict__ W_enc,
                                                  const float* __restrict__ b_enc,
                                                  const float* __restrict__ W_dec,
                                                  const float* __restrict__ b_dec,
                                                  float* __restrict__ z,
                                                  __nv_bfloat16* __restrict__ Z2a,
                                                  float* __restrict__ preds) {
    const int tid = threadIdx.x;
    const int lane = tid & 31;
    const int r = blockIdx.x * 8 + (tid >> 5);
    const int n = r >> 6, b = r & 63;
    const float* x = x_seq + (size_t)(b * NN + n) * TT * FF;  // t = 0
    const float x0 = x[0], x1 = x[1], x2 = x[2];
    const int h0 = 2 * lane, h1 = h0 + 1;
    const float za = b_enc[h0] + x0 * W_enc[h0] + x1 * W_enc[64 + h0] + x2 * W_enc[128 + h0];
    const float zb = b_enc[h1] + x0 * W_enc[h1] + x1 * W_enc[64 + h1] + x2 * W_enc[128 + h1];
    *reinterpret_cast<float2*>(z + (size_t)r * HH + h0) = make_float2(za, zb);
    split_store2(Z2a, n, (b << 6) + h0, za, zb);
    const float p = warp_sum(za * W_dec[h0] + zb * W_dec[h1]);
    if (lane == 0) preds[(size_t)(b * NN + n) * TT + 0] = p + b_dec[0];
}

// ---------------------------------------------------------------------------
extern "C" void kernel_launch(void* const* d_in, const int* in_sizes, int n_in,
                              void* d_out, int out_size) {
    const float* x_seq   = (const float*)d_in[0];
    const float* obs_mask= (const float*)d_in[1];
    const float* A       = (const float*)d_in[2];
    const float* W_enc   = (const float*)d_in[3];
    const float* b_enc   = (const float*)d_in[4];
    const float* W_gc1   = (const float*)d_in[5];
    const float* W_gc2   = (const float*)d_in[6];
    const float* ln_g    = (const float*)d_in[7];
    const float* ln_b    = (const float*)d_in[8];
    const float* W_obs   = (const float*)d_in[9];
    const float* b_obs   = (const float*)d_in[10];
    const float* W_gate  = (const float*)d_in[11];
    const float* b_gate  = (const float*)d_in[12];
    const float* W_dec   = (const float*)d_in[13];
    const float* b_dec   = (const float*)d_in[14];
    float* preds = (float*)d_out;

    float *z, *wcomb, *bgc;
    __nv_bfloat16 *a2, *z2a, *z2b;
    cudaGetSymbolAddress((void**)&z,    g_z);
    cudaGetSymbolAddress((void**)&a2,   g_A2);
    cudaGetSymbolAddress((void**)&z2a,  g_Z2a);
    cudaGetSymbolAddress((void**)&z2b,  g_Z2b);
    cudaGetSymbolAddress((void**)&wcomb,g_wcomb);
    cudaGetSymbolAddress((void**)&bgc,  g_bgc);

    cudaFuncSetAttribute(stepA_kernel, cudaFuncAttributeMaxDynamicSharedMemorySize, DSMEM);
    cudaFuncSetAttribute(stepB_kernel, cudaFuncAttributeMaxDynamicSharedMemorySize, DSMEM);

    prepA_kernel<<<(MPAD * KA + 255) / 256, 256>>>(A, a2);
    prepW_kernel<<<1, 64>>>(W_gate, W_obs, b_obs, b_gate, wcomb, bgc);
    enc_kernel<<<ROWS / 8, 256>>>(x_seq, W_enc, b_enc, W_dec, b_dec, z, z2a, preds);

    const dim3 ggrid(COLS / NT, MPAD / MT);   // 64 x 3
    for (int t = 0; t < TT - 1; t++) {
        stepA_kernel<<<ggrid, 256, DSMEM>>>(a2, z2a, W_gc1, z2b);
        stepB_kernel<<<ggrid, 256, DSMEM>>>(a2, z2b, W_gc2, W_gate,
                                            ln_g, ln_b, W_obs, b_obs, wcomb, bgc,
                                            W_dec, b_dec, x_seq, obs_mask,
                                            z, z2a, preds, t + 1);
    }
}

// round 17
// speedup vs baseline: 1.6953x; 1.1370x over previous
#include <cuda_runtime.h>
#include <cuda_bf16.h>
#include <stdint.h>
#include <math.h>

// Problem constants
#define BB 64
#define NN 307
#define TT 64
#define FF 3
#define HH 64
#define ROWS (NN * BB)          // 19648
#define COLS (BB * HH)          // 4096

// Split-bf16 A-GEMM: A2 = [A_hi | A_lo] (320x640), Z2 = [Z_hi ; Z_lo] (640x4096 k-major)
#define KSEG 320
#define KA   640
#define MPAD 320
#define KC   64
#define NCH  15
#define MT   64
#define NT   64
#define PA   72      // smem pitch (bf16) = 144B -> ldmatrix conflict-free
#define PTF_T 66     // smT pitch (fp32)
#define PTF_W 68     // smW pitch (fp32)

// 3-stage cp.async pipeline: per stage A[64xPA] + B[64xPA] bf16 = 18432 B
#define TILE_B   (64 * PA * 2)          // 9216
#define STAGE_B  (2 * TILE_B)           // 18432
#define DSMEM    (3 * STAGE_B)          // 55296
// phase2 union: smT fp32 [0..16896) + smW fp32 [16896..34304)
#define OFF_SMW_F (64 * PTF_T * 4)      // 16896

// Persistent scratch (__device__ globals; zero-init -> padding rows stay 0 forever)
__device__ __align__(256) float         g_z   [ROWS * HH];
__device__ __align__(256) __nv_bfloat16 g_A2  [MPAD * KA];
__device__ __align__(256) __nv_bfloat16 g_Z2a [KA * COLS];   // z (F1 input)
__device__ __align__(256) __nv_bfloat16 g_Z2b [KA * COLS];   // h (F2 input)
__device__ __align__(256) float         g_wcomb[3 * 64];     // W_obs @ Wg_bot
__device__ __align__(256) float         g_bgc  [64];         // b_gate + b_obs @ Wg_bot

// ---------------------------------------------------------------------------
// PTX helpers
// ---------------------------------------------------------------------------
__device__ __forceinline__ uint32_t smem_u32(const void* p) {
    uint32_t a;
    asm("{ .reg .u64 t; cvta.to.shared.u64 t, %1; cvt.u32.u64 %0, t; }" : "=r"(a) : "l"(p));
    return a;
}
__device__ __forceinline__ void cp16(uint32_t s, const void* g) {
    asm volatile("cp.async.cg.shared.global [%0], [%1], 16;" :: "r"(s), "l"(g));
}
__device__ __forceinline__ void cp_commit() {
    asm volatile("cp.async.commit_group;" ::: "memory");
}
__device__ __forceinline__ void cp_wait1() {
    asm volatile("cp.async.wait_group 1;" ::: "memory");
}
__device__ __forceinline__ void cp_wait0() {
    asm volatile("cp.async.wait_group 0;" ::: "memory");
}
__device__ __forceinline__ void ldm_x4(uint32_t* r, uint32_t addr) {
    asm volatile("ldmatrix.sync.aligned.m8n8.x4.shared.b16 {%0,%1,%2,%3}, [%4];"
                 : "=r"(r[0]), "=r"(r[1]), "=r"(r[2]), "=r"(r[3]) : "r"(addr));
}
__device__ __forceinline__ void ldm_x2t(uint32_t* r, uint32_t addr) {
    asm volatile("ldmatrix.sync.aligned.m8n8.x2.trans.shared.b16 {%0,%1}, [%2];"
                 : "=r"(r[0]), "=r"(r[1]) : "r"(addr));
}
__device__ __forceinline__ void mma16816(float* d, const uint32_t* a, const uint32_t* b,
                                         const float* c) {
    asm volatile("mma.sync.aligned.m16n8k16.row.col.f32.bf16.bf16.f32 "
                 "{%0,%1,%2,%3}, {%4,%5,%6,%7}, {%8,%9}, {%10,%11,%12,%13};"
                 : "=f"(d[0]), "=f"(d[1]), "=f"(d[2]), "=f"(d[3])
                 : "r"(a[0]), "r"(a[1]), "r"(a[2]), "r"(a[3]),
                   "r"(b[0]), "r"(b[1]),
                   "f"(c[0]), "f"(c[1]), "f"(c[2]), "f"(c[3]));
}

// Split-bf16 store into k-major [640 x 4096]: hi at row n, lo at row n+320
__device__ __forceinline__ void split_store2(__nv_bfloat16* base, int n, int c,
                                             float v0, float v1) {
    const __nv_bfloat16 h0 = __float2bfloat16(v0);
    const __nv_bfloat16 h1 = __float2bfloat16(v1);
    const __nv_bfloat16 l0 = __float2bfloat16(v0 - __bfloat162float(h0));
    const __nv_bfloat16 l1 = __float2bfloat16(v1 - __bfloat162float(h1));
    __nv_bfloat162 hh; hh.x = h0; hh.y = h1;
    __nv_bfloat162 ll; ll.x = l0; ll.y = l1;
    *(__nv_bfloat162*)(base + (size_t)n * COLS + c)          = hh;
    *(__nv_bfloat162*)(base + (size_t)(n + KSEG) * COLS + c) = ll;
}

// ---------------------------------------------------------------------------
// cp.async one pipeline stage: A tile 64xKC rows m0.., B tile (k-major) 64 k-rows
// ---------------------------------------------------------------------------
__device__ __forceinline__ void issue_stage(const __nv_bfloat16* __restrict__ Ag,
                                            const __nv_bfloat16* __restrict__ Bg,
                                            int ch, int tid,
                                            uint32_t smA, uint32_t smB) {
    const int seg = ch / 5;
    const int kk0 = (ch % 5) * KC;
    const int a_off = kk0 + ((seg == 1) ? KSEG : 0);
    const int b_off = kk0 + ((seg == 2) ? KSEG : 0);
#pragma unroll
    for (int i = 0; i < 2; i++) {
        const int idx = tid + i * 256;        // 0..511
        const int row = idx >> 3;             // 0..63
        const int q = idx & 7;
        cp16(smA + (row * PA + q * 8) * 2, Ag + (size_t)row * KA + a_off + q * 8);
        cp16(smB + (row * PA + q * 8) * 2, Bg + (size_t)(b_off + row) * COLS + q * 8);
    }
    cp_commit();
}

// ---------------------------------------------------------------------------
// Main split-bf16 A-GEMM: 64x64 tile, 8 warps (2m x 4n), warp tile 32x16,
// 3-stage cp.async pipeline, ldmatrix fragment loads.
// ---------------------------------------------------------------------------
__device__ __forceinline__ void main_gemm(const __nv_bfloat16* __restrict__ Ag,
                                          const __nv_bfloat16* __restrict__ Bg,
                                          char* dsm, int tid,
                                          float acc[2][2][4]) {
    const int lane = tid & 31, wid = tid >> 5;
    const int mw = wid & 1, nw = wid >> 1;    // 2 x 4 warp grid

#pragma unroll
    for (int fm = 0; fm < 2; fm++)
#pragma unroll
        for (int fn = 0; fn < 2; fn++)
#pragma unroll
            for (int j = 0; j < 4; j++) acc[fm][fn][j] = 0.f;

    uint32_t smA[3], smB[3];
#pragma unroll
    for (int s = 0; s < 3; s++) {
        smA[s] = smem_u32(dsm + s * STAGE_B);
        smB[s] = smA[s] + TILE_B;
    }

    // per-lane ldmatrix base offsets (bytes)
    const uint32_t a_base = ((mw * 32 + (lane & 15)) * PA + (lane >> 4) * 8) * 2;
    const uint32_t b_base = ((lane & 15) * PA + nw * 16) * 2;

    issue_stage(Ag, Bg, 0, tid, smA[0], smB[0]);
    issue_stage(Ag, Bg, 1, tid, smA[1], smB[1]);

    for (int ch = 0; ch < NCH; ch++) {
        if (ch < NCH - 2) cp_wait1(); else cp_wait0();
        __syncthreads();
        const int cur = ch % 3;
        const uint32_t sA = smA[cur], sB = smB[cur];
#pragma unroll
        for (int ks = 0; ks < 4; ks++) {
            uint32_t af[2][4], bf[2][2];
#pragma unroll
            for (int fm = 0; fm < 2; fm++)
                ldm_x4(af[fm], sA + a_base + (fm * 16 * PA + ks * 16) * 2);
#pragma unroll
            for (int fn = 0; fn < 2; fn++)
                ldm_x2t(bf[fn], sB + b_base + (ks * 16 * PA + fn * 8) * 2);
#pragma unroll
            for (int fm = 0; fm < 2; fm++)
#pragma unroll
                for (int fn = 0; fn < 2; fn++)
                    mma16816(acc[fm][fn], af[fm], bf[fn], acc[fm][fn]);
        }
        if (ch + 2 < NCH)
            issue_stage(Ag, Bg, ch + 2, tid, smA[(ch + 2) % 3], smB[(ch + 2) % 3]);
    }
    __syncthreads();   // protect phase2 smem reuse
}

// Stage acc tile (64x64) into smT as FP32
__device__ __forceinline__ void stage_acc_f32(float* smT, const float acc[2][2][4],
                                              int tid) {
    const int lane = tid & 31, wid = tid >> 5;
    const int mw = wid & 1, nw = wid >> 1;
    const int g = lane >> 2, q = lane & 3;
#pragma unroll
    for (int fm = 0; fm < 2; fm++) {
        const int r1 = mw * 32 + fm * 16 + g;
#pragma unroll
        for (int fn = 0; fn < 2; fn++) {
            const int col = nw * 16 + fn * 8 + 2 * q;
            *(float2*)(smT + r1 * PTF_T + col)       = make_float2(acc[fm][fn][0], acc[fm][fn][1]);
            *(float2*)(smT + (r1 + 8) * PTF_T + col) = make_float2(acc[fm][fn][2], acc[fm][fn][3]);
        }
    }
}

// Stage a [64x64] fp32 weight (k-major, W[k][j]) into smW (pitch PTF_W)
__device__ __forceinline__ void stage_w_f32(float* smW, const float* __restrict__ W, int tid) {
#pragma unroll
    for (int i = tid; i < 4096; i += 256)
        smW[(i >> 6) * PTF_W + (i & 63)] = W[i];
}

// fp32 small matmul: v[2][8] = smT(rows r0..r0+1) @ smW ; thread cols cg*8..cg*8+7
__device__ __forceinline__ void small_f32(const float* smT, const float* smW,
                                          int r0, int cg, float v[2][8]) {
#pragma unroll
    for (int i = 0; i < 2; i++)
#pragma unroll
        for (int j = 0; j < 8; j++) v[i][j] = 0.f;
    for (int k = 0; k < 64; k++) {
        const float4 wa = *(const float4*)(smW + k * PTF_W + cg * 8);
        const float4 wb = *(const float4*)(smW + k * PTF_W + cg * 8 + 4);
#pragma unroll
        for (int i = 0; i < 2; i++) {
            const float tv = smT[(r0 + i) * PTF_T + k];
            v[i][0] += tv * wa.x; v[i][1] += tv * wa.y;
            v[i][2] += tv * wa.z; v[i][3] += tv * wa.w;
            v[i][4] += tv * wb.x; v[i][5] += tv * wb.y;
            v[i][6] += tv * wb.z; v[i][7] += tv * wb.w;
        }
    }
}

__device__ __forceinline__ float red8(float v) {
    v += __shfl_xor_sync(0xffffffffu, v, 1);
    v += __shfl_xor_sync(0xffffffffu, v, 2);
    v += __shfl_xor_sync(0xffffffffu, v, 4);
    return v;
}

// ---------------------------------------------------------------------------
// F1: AZ = A@Z2a (split-bf16 mma) ; h = tanh(AZ @ W1) (fp32) -> Z2b
// ---------------------------------------------------------------------------
__global__ void __launch_bounds__(256, 3) stepA_kernel(const __nv_bfloat16* __restrict__ A2,
                                                       const __nv_bfloat16* __restrict__ Z2a,
                                                       const float* __restrict__ W1,
                                                       __nv_bfloat16* __restrict__ Z2b) {
    extern __shared__ char dsm[];
    float* smT = (float*)dsm;
    float* smW = (float*)(dsm + OFF_SMW_F);

    const int tid = threadIdx.x;
    const int bb = blockIdx.x, m0 = blockIdx.y * MT;

    float acc[2][2][4];
    main_gemm(A2 + (size_t)m0 * KA, Z2a + bb * 64, dsm, tid, acc);

    stage_acc_f32(smT, acc, tid);
    stage_w_f32(smW, W1, tid);
    __syncthreads();

    const int cg = tid & 7, r0 = (tid >> 3) * 2;
    float v[2][8];
    small_f32(smT, smW, r0, cg, v);

#pragma unroll
    for (int i = 0; i < 2; i++) {
        const int n = m0 + r0 + i;
        if (n < NN) {
#pragma unroll
            for (int j = 0; j < 8; j += 2)
                split_store2(Z2b, n, (bb << 6) + cg * 8 + j,
                             tanhf(v[i][j]), tanhf(v[i][j + 1]));
        }
    }
}

// ---------------------------------------------------------------------------
// F2: AH = A@Z2b ; t = tanh(AH @ W2) ; delta = LN(t) ; z1 = 2z + delta ;
//     gate = sigmoid(z1@Wg_top + x@Wcomb + bgc) ; z = z1 + gate*(zo-z1)*mask
//     -> g_z, Z2a, preds.   All pointwise matmuls in fp32.
// ---------------------------------------------------------------------------
__global__ void __launch_bounds__(256, 2) stepB_kernel(const __nv_bfloat16* __restrict__ A2,
                                                       const __nv_bfloat16* __restrict__ Z2b,
                                                       const float* __restrict__ W2,
                                                       const float* __restrict__ Wg,
                                                       const float* __restrict__ ln_g,
                                                       const float* __restrict__ ln_b,
                                                       const float* __restrict__ W_obs,
                                                       const float* __restrict__ b_obs,
                                                       const float* __restrict__ wcomb,
                                                       const float* __restrict__ bgc,
                                                       const float* __restrict__ W_dec,
                                                       const float* __restrict__ b_dec,
                                                       const float* __restrict__ x_seq,
                                                       const float* __restrict__ obs_mask,
                                                       float* __restrict__ z,
                                                       __nv_bfloat16* __restrict__ Z2a,
                                                       float* __restrict__ preds,
                                                       int t1) {
    extern __shared__ char dsm[];
    float* smT = (float*)dsm;
    float* smW = (float*)(dsm + OFF_SMW_F);
    __shared__ float cs_lng[64], cs_lnb[64], cs_wo[192], cs_bo[64];
    __shared__ float cs_bgc[64], cs_wc[192], cs_wd[64];

    const int tid = threadIdx.x;
    const int bb = blockIdx.x, m0 = blockIdx.y * MT;

    if (tid < 64) {
        cs_lng[tid] = ln_g[tid]; cs_lnb[tid] = ln_b[tid];
        cs_bo[tid] = b_obs[tid]; cs_bgc[tid] = bgc[tid]; cs_wd[tid] = W_dec[tid];
    }
    if (tid < 192) { cs_wo[tid] = W_obs[tid]; cs_wc[tid] = wcomb[tid]; }
    // covered by the first __syncthreads inside main_gemm

    float acc[2][2][4];
    main_gemm(A2 + (size_t)m0 * KA, Z2b + bb * 64, dsm, tid, acc);

    stage_acc_f32(smT, acc, tid);
    stage_w_f32(smW, W2, tid);
    __syncthreads();

    const int cg = tid & 7, r0 = (tid >> 3) * 2;
    float v[2][8];
    small_f32(smT, smW, r0, cg, v);      // AH @ W2

    // tanh
#pragma unroll
    for (int i = 0; i < 2; i++)
#pragma unroll
        for (int j = 0; j < 8; j++) v[i][j] = tanhf(v[i][j]);

    // LayerNorm per row (reduce across the 8 cg lanes)
    float mu[2], rs[2];
#pragma unroll
    for (int i = 0; i < 2; i++) {
        float s = 0.f;
#pragma unroll
        for (int j = 0; j < 8; j++) s += v[i][j];
        mu[i] = red8(s) * (1.f / 64.f);
        float vr = 0.f;
#pragma unroll
        for (int j = 0; j < 8; j++) { const float d = v[i][j] - mu[i]; vr += d * d; }
        rs[i] = rsqrtf(red8(vr) * (1.f / 64.f) + 1e-5f);
    }

    // z1 = 2z + delta
#pragma unroll
    for (int i = 0; i < 2; i++) {
        const int n = m0 + r0 + i;
        float zr[8] = {0.f, 0.f, 0.f, 0.f, 0.f, 0.f, 0.f, 0.f};
        if (n < NN) {
            const float* zp = z + (((size_t)(n << 6) + bb) << 6) + cg * 8;
            const float4 za = *(const float4*)(zp);
            const float4 zb2 = *(const float4*)(zp + 4);
            zr[0] = za.x; zr[1] = za.y; zr[2] = za.z; zr[3] = za.w;
            zr[4] = zb2.x; zr[5] = zb2.y; zr[6] = zb2.z; zr[7] = zb2.w;
        }
#pragma unroll
        for (int j = 0; j < 8; j++) {
            const int c = cg * 8 + j;
            v[i][j] = 2.f * zr[j] + (v[i][j] - mu[i]) * rs[i] * cs_lng[c] + cs_lnb[c];
        }
    }

    // gate logit matmul in fp32: stage z1, stage Wg_top, multiply
    __syncthreads();
#pragma unroll
    for (int i = 0; i < 2; i++)
#pragma unroll
        for (int j = 0; j < 8; j += 2)
            *(float2*)(smT + (r0 + i) * PTF_T + cg * 8 + j) = make_float2(v[i][j], v[i][j + 1]);
    stage_w_f32(smW, Wg, tid);   // rows 0..63 of W_gate (z1 part)
    __syncthreads();

    float lg[2][8];
    small_f32(smT, smW, r0, cg, lg);

    const float bdec = b_dec[0];
#pragma unroll
    for (int i = 0; i < 2; i++) {
        const int n = m0 + r0 + i;
        float x0 = 0.f, x1 = 0.f, x2 = 0.f, m = 0.f;
        if (n < NN) {
            const float* xp = x_seq + ((size_t)(bb * NN + n) * TT + t1) * FF;
            x0 = xp[0]; x1 = xp[1]; x2 = xp[2];
            m = obs_mask[bb * NN + n];
        }
        float p = 0.f;
#pragma unroll
        for (int j = 0; j < 8; j++) {
            const int c = cg * 8 + j;
            const float lgv = lg[i][j] + x0 * cs_wc[c] + x1 * cs_wc[64 + c]
                            + x2 * cs_wc[128 + c] + cs_bgc[c];
            const float gate = 1.f / (1.f + __expf(-lgv));
            const float zo = cs_bo[c] + x0 * cs_wo[c] + x1 * cs_wo[64 + c]
                           + x2 * cs_wo[128 + c];
            const float z1v = v[i][j];
            const float zf = z1v + gate * (zo - z1v) * m;
            v[i][j] = zf;
            p += zf * cs_wd[c];
        }
        if (n < NN) {
            float* zp = z + (((size_t)(n << 6) + bb) << 6) + cg * 8;
            *(float4*)(zp)     = make_float4(v[i][0], v[i][1], v[i][2], v[i][3]);
            *(float4*)(zp + 4) = make_float4(v[i][4], v[i][5], v[i][6], v[i][7]);
#pragma unroll
            for (int j = 0; j < 8; j += 2)
                split_store2(Z2a, n, (bb << 6) + cg * 8 + j, v[i][j], v[i][j + 1]);
        }
        p = red8(p);
        if (cg == 0 && n < NN) preds[(size_t)(bb * NN + n) * TT + t1] = p + bdec;
    }
}

// ---------------------------------------------------------------------------
// prepA: A2 = [A_hi | A_lo] (320 x 640 bf16)
// ---------------------------------------------------------------------------
__global__ void __launch_bounds__(256) prepA_kernel(const float* __restrict__ A,
                                                    __nv_bfloat16* __restrict__ A2) {
    const int idx = blockIdx.x * 256 + threadIdx.x;
    if (idx >= MPAD * KA) return;
    const int m = idx / KA, k = idx % KA;
    const int kk = (k >= KSEG) ? k - KSEG : k;
    const float v = (m < NN && kk < NN) ? A[m * NN + kk] : 0.f;
    const __nv_bfloat16 hi = __float2bfloat16(v);
    A2[idx] = (k >= KSEG) ? __float2bfloat16(v - __bfloat162float(hi)) : hi;
}

// ---------------------------------------------------------------------------
// prepW: Wcomb = Wo @ Wg_bot ; bgc = bg + bo @ Wg_bot  (all fp32)
// ---------------------------------------------------------------------------
__global__ void prepW_kernel(const float* __restrict__ Wg,
                             const float* __restrict__ Wo,
                             const float* __restrict__ bo,
                             const float* __restrict__ bg,
                             float* __restrict__ wcomb,
                             float* __restrict__ bgc) {
    const int j = threadIdx.x;
    if (j >= 64) return;
    float s0 = 0.f, s1 = 0.f, s2 = 0.f, sb = 0.f;
    for (int h = 0; h < 64; h++) {
        const float wg = Wg[(64 + h) * 64 + j];
        s0 += Wo[h] * wg;
        s1 += Wo[64 + h] * wg;
        s2 += Wo[128 + h] * wg;
        sb += bo[h] * wg;
    }
    wcomb[j] = s0; wcomb[64 + j] = s1; wcomb[128 + j] = s2;
    bgc[j] = bg[j] + sb;
}

// ---------------------------------------------------------------------------
// Encoder: z0 + preds[...,0]; seeds Z2a
// ---------------------------------------------------------------------------
__device__ __forceinline__ float warp_sum(float v) {
#pragma unroll
    for (int o = 16; o > 0; o >>= 1) v += __shfl_xor_sync(0xffffffffu, v, o);
    return v;
}

__global__ void __launch_bounds__(256) enc_kernel(const float* __restrict__ x_seq,
                                                  const float* __restrict__ W_enc,
                                                  const float* __restrict__ b_enc,
                                                  const float* __restrict__ W_dec,
                                                  const float* __restrict__ b_dec,
                                                  float* __restrict__ z,
                                                  __nv_bfloat16* __restrict__ Z2a,
                                                  float* __restrict__ preds) {
    const int tid = threadIdx.x;
    const int lane = tid & 31;
    const int r = blockIdx.x * 8 + (tid >> 5);
    const int n = r >> 6, b = r & 63;
    const float* x = x_seq + (size_t)(b * NN + n) * TT * FF;  // t = 0
    const float x0 = x[0], x1 = x[1], x2 = x[2];
    const int h0 = 2 * lane, h1 = h0 + 1;
    const float za = b_enc[h0] + x0 * W_enc[h0] + x1 * W_enc[64 + h0] + x2 * W_enc[128 + h0];
    const float zb = b_enc[h1] + x0 * W_enc[h1] + x1 * W_enc[64 + h1] + x2 * W_enc[128 + h1];
    *reinterpret_cast<float2*>(z + (size_t)r * HH + h0) = make_float2(za, zb);
    split_store2(Z2a, n, (b << 6) + h0, za, zb);
    const float p = warp_sum(za * W_dec[h0] + zb * W_dec[h1]);
    if (lane == 0) preds[(size_t)(b * NN + n) * TT + 0] = p + b_dec[0];
}

// ---------------------------------------------------------------------------
extern "C" void kernel_launch(void* const* d_in, const int* in_sizes, int n_in,
                              void* d_out, int out_size) {
    const float* x_seq   = (const float*)d_in[0];
    const float* obs_mask= (const float*)d_in[1];
    const float* A       = (const float*)d_in[2];
    const float* W_enc   = (const float*)d_in[3];
    const float* b_enc   = (const float*)d_in[4];
    const float* W_gc1   = (const float*)d_in[5];
    const float* W_gc2   = (const float*)d_in[6];
    const float* ln_g    = (const float*)d_in[7];
    const float* ln_b    = (const float*)d_in[8];
    const float* W_obs   = (const float*)d_in[9];
    const float* b_obs   = (const float*)d_in[10];
    const float* W_gate  = (const float*)d_in[11];
    const float* b_gate  = (const float*)d_in[12];
    const float* W_dec   = (const float*)d_in[13];
    const float* b_dec   = (const float*)d_in[14];
    float* preds = (float*)d_out;

    float *z, *wcomb, *bgc;
    __nv_bfloat16 *a2, *z2a, *z2b;
    cudaGetSymbolAddress((void**)&z,    g_z);
    cudaGetSymbolAddress((void**)&a2,   g_A2);
    cudaGetSymbolAddress((void**)&z2a,  g_Z2a);
    cudaGetSymbolAddress((void**)&z2b,  g_Z2b);
    cudaGetSymbolAddress((void**)&wcomb,g_wcomb);
    cudaGetSymbolAddress((void**)&bgc,  g_bgc);

    cudaFuncSetAttribute(stepA_kernel, cudaFuncAttributeMaxDynamicSharedMemorySize, DSMEM);
    cudaFuncSetAttribute(stepB_kernel, cudaFuncAttributeMaxDynamicSharedMemorySize, DSMEM);

    prepA_kernel<<<(MPAD * KA + 255) / 256, 256>>>(A, a2);
    prepW_kernel<<<1, 64>>>(W_gate, W_obs, b_obs, b_gate, wcomb, bgc);
    enc_kernel<<<ROWS / 8, 256>>>(x_seq, W_enc, b_enc, W_dec, b_dec, z, z2a, preds);

    const dim3 ggrid(COLS / NT, MPAD / MT);   // 64 x 5
    for (int t = 0; t < TT - 1; t++) {
        stepA_kernel<<<ggrid, 256, DSMEM>>>(a2, z2a, W_gc1, z2b);
        stepB_kernel<<<ggrid, 256, DSMEM>>>(a2, z2b, W_gc2, W_gate,
                                            ln_g, ln_b, W_obs, b_obs, wcomb, bgc,
                                            W_dec, b_dec, x_seq, obs_mask,
                                            z, z2a, preds, t + 1);
    }
}